// round 1
// baseline (speedup 1.0000x reference)
#include <cuda_runtime.h>
#include <math.h>

// Problem constants (fixed shapes per reference)
#define BB 4
#define SS 2048
#define DD 1024
#define HH 16
#define HD 64
#define MTOT (BB * SS)          // 8192 rows
#define ELEMS (BB * SS * DD)    // 8,388,608

// ---------------------------------------------------------------------------
// Scratch (allocation-free: __device__ globals)
// ---------------------------------------------------------------------------
__device__ float g_xr[ELEMS];   // mixed r-input; later reused for normed output
__device__ float g_xk[ELEMS];
__device__ float g_xv[ELEMS];
__device__ float g_r[ELEMS];
__device__ float g_k[ELEMS];
__device__ float g_v[ELEMS];
__device__ float g_wkv[ELEMS];  // wkv; later overwritten in-place with sigmoid(r)*wkv

// ---------------------------------------------------------------------------
// Kernel 1: token shift + time mixing -> xr, xk, xv  (float4 vectorized)
// ---------------------------------------------------------------------------
__global__ void mix_kernel(const float* __restrict__ x,
                           const float* __restrict__ tmr,
                           const float* __restrict__ tmk,
                           const float* __restrict__ tmv) {
    int idx = blockIdx.x * blockDim.x + threadIdx.x;   // float4 index
    const int TOT4 = ELEMS / 4;
    if (idx >= TOT4) return;
    const int D4 = DD / 4;
    int d4 = idx % D4;
    int bs = idx / D4;
    int s  = bs % SS;

    const float4* x4 = (const float4*)x;
    float4 xv_ = x4[idx];
    float4 sh  = (s > 0) ? x4[idx - D4] : make_float4(0.f, 0.f, 0.f, 0.f);
    float4 mr = ((const float4*)tmr)[d4];
    float4 mk = ((const float4*)tmk)[d4];
    float4 mv = ((const float4*)tmv)[d4];

    float4 orr, okk, ovv;
    orr.x = xv_.x * mr.x + sh.x * (1.f - mr.x);
    orr.y = xv_.y * mr.y + sh.y * (1.f - mr.y);
    orr.z = xv_.z * mr.z + sh.z * (1.f - mr.z);
    orr.w = xv_.w * mr.w + sh.w * (1.f - mr.w);
    okk.x = xv_.x * mk.x + sh.x * (1.f - mk.x);
    okk.y = xv_.y * mk.y + sh.y * (1.f - mk.y);
    okk.z = xv_.z * mk.z + sh.z * (1.f - mk.z);
    okk.w = xv_.w * mk.w + sh.w * (1.f - mk.w);
    ovv.x = xv_.x * mv.x + sh.x * (1.f - mv.x);
    ovv.y = xv_.y * mv.y + sh.y * (1.f - mv.y);
    ovv.z = xv_.z * mv.z + sh.z * (1.f - mv.z);
    ovv.w = xv_.w * mv.w + sh.w * (1.f - mv.w);

    ((float4*)g_xr)[idx] = orr;
    ((float4*)g_xk)[idx] = okk;
    ((float4*)g_xv)[idx] = ovv;
}

// ---------------------------------------------------------------------------
// Kernel 2: fp32 GEMM  C[M,N] = A[M,K] * B[N,K]^T   (both row-major, K contig)
// Tile 128x64x16, 256 threads, 8x4 per-thread microtile.
// ---------------------------------------------------------------------------
__global__ __launch_bounds__(256)
void gemm128x64(const float* __restrict__ A, const float* __restrict__ Bm,
                float* __restrict__ C, int M, int N, int K) {
    __shared__ float As[16][132];  // [k][m], pad keeps 16B alignment, few conflicts
    __shared__ float Bs[16][68];   // [k][n]

    const int tid = threadIdx.x;
    const int tx = tid & 15;       // 0..15  -> 4 cols each
    const int ty = tid >> 4;       // 0..15  -> 8 rows each
    const int bm = blockIdx.y * 128;
    const int bn = blockIdx.x * 64;

    const float* Aptr = A + (size_t)bm * K;
    const float* Bptr = Bm + (size_t)bn * K;

    float acc[8][4];
#pragma unroll
    for (int i = 0; i < 8; i++)
#pragma unroll
        for (int j = 0; j < 4; j++) acc[i][j] = 0.f;

    for (int k0 = 0; k0 < K; k0 += 16) {
        // load A tile: 128x16 = 2048 floats = 2 x float4 per thread
#pragma unroll
        for (int l = 0; l < 2; l++) {
            int lin = tid + l * 256;
            int row = lin >> 2;             // 0..127
            int cg  = (lin & 3) << 2;       // 0,4,8,12
            float4 a = *(const float4*)(Aptr + (size_t)row * K + k0 + cg);
            As[cg + 0][row] = a.x;
            As[cg + 1][row] = a.y;
            As[cg + 2][row] = a.z;
            As[cg + 3][row] = a.w;
        }
        // load B tile: 64x16 = 1024 floats = 1 x float4 per thread
        {
            int row = tid >> 2;             // 0..63
            int cg  = (tid & 3) << 2;
            float4 b = *(const float4*)(Bptr + (size_t)row * K + k0 + cg);
            Bs[cg + 0][row] = b.x;
            Bs[cg + 1][row] = b.y;
            Bs[cg + 2][row] = b.z;
            Bs[cg + 3][row] = b.w;
        }
        __syncthreads();

#pragma unroll
        for (int kk = 0; kk < 16; kk++) {
            float a[8], bfr[4];
#pragma unroll
            for (int i = 0; i < 8; i++) a[i] = As[kk][ty * 8 + i];
#pragma unroll
            for (int j = 0; j < 4; j++) bfr[j] = Bs[kk][tx * 4 + j];
#pragma unroll
            for (int i = 0; i < 8; i++)
#pragma unroll
                for (int j = 0; j < 4; j++) acc[i][j] = fmaf(a[i], bfr[j], acc[i][j]);
        }
        __syncthreads();
    }

#pragma unroll
    for (int i = 0; i < 8; i++) {
        float4 o;
        o.x = acc[i][0]; o.y = acc[i][1]; o.z = acc[i][2]; o.w = acc[i][3];
        *(float4*)(C + (size_t)(bm + ty * 8 + i) * N + bn + tx * 4) = o;
    }
}

// ---------------------------------------------------------------------------
// Kernel 3: WKV recurrence. One thread per (b, channel). Serial over S.
// ---------------------------------------------------------------------------
__global__ void wkv_kernel(const float* __restrict__ td,
                           const float* __restrict__ tf) {
    int gid = blockIdx.x * blockDim.x + threadIdx.x;  // 0..4095
    if (gid >= BB * DD) return;
    int c = gid % DD;
    int b = gid / DD;

    const float w = -expf(td[c]);   // time_decay flattened (H,HD) == channel c
    const float u = tf[c];

    const float* kp = g_k   + (size_t)b * SS * DD + c;
    const float* vp = g_v   + (size_t)b * SS * DD + c;
    float*       op = g_wkv + (size_t)b * SS * DD + c;

    float aa = 0.f, bb = -1e38f;
    float kt = kp[0], vt = vp[0];
#pragma unroll 1
    for (int t = 0; t < SS; t++) {
        float kn = 0.f, vn = 0.f;
        if (t + 1 < SS) {               // prefetch next step (off critical path)
            kn = kp[(size_t)(t + 1) * DD];
            vn = vp[(size_t)(t + 1) * DD];
        }
        float wk = kt + u;
        float p  = fmaxf(bb, wk);
        float e1 = expf(bb - p);
        float e2 = expf(wk - p);
        op[(size_t)t * DD] = (e1 * aa + e2 * vt) / (e1 + e2 + 1e-8f);

        float ww  = bb + w;
        float p2  = fmaxf(ww, kt);
        float e1b = expf(ww - p2);
        float e2b = expf(kt - p2);
        aa = e1b * aa + e2b * vt;
        bb = p2 + logf(e1b + e2b + 1e-8f);

        kt = kn; vt = vn;
    }
}

// ---------------------------------------------------------------------------
// Kernel 4: y = sigmoid(r) * wkv (in place into g_wkv), then GroupNorm over
// (S, HD) per (b,h) group; normed written into g_xr (reused).
// One block per (b,h) group.
// ---------------------------------------------------------------------------
__global__ __launch_bounds__(256)
void gn_kernel(const float* __restrict__ gamma, const float* __restrict__ beta) {
    const int g = blockIdx.x;          // 0..63
    const int b = g / HH;
    const int h = g % HH;
    const size_t base = (size_t)b * SS * DD + (size_t)h * HD;
    const int tid = threadIdx.x;
    const int NELEM = SS * HD;         // 131072

    float sum = 0.f, sq = 0.f;
    for (int j = tid; j < NELEM; j += 256) {
        int s = j >> 6, i = j & 63;
        size_t off = base + (size_t)s * DD + i;
        float rv = g_r[off];
        float wv = g_wkv[off];
        float y  = wv / (1.f + __expf(-rv));
        g_wkv[off] = y;
        sum += y;
        sq  += y * y;
    }

    __shared__ float red1[256];
    __shared__ float red2[256];
    red1[tid] = sum;
    red2[tid] = sq;
    __syncthreads();
#pragma unroll
    for (int off = 128; off > 0; off >>= 1) {
        if (tid < off) {
            red1[tid] += red1[tid + off];
            red2[tid] += red2[tid + off];
        }
        __syncthreads();
    }

    __shared__ float s_mean, s_rstd;
    if (tid == 0) {
        float mean = red1[0] / (float)NELEM;
        float var  = red2[0] / (float)NELEM - mean * mean;
        s_mean = mean;
        s_rstd = rsqrtf(var + 1e-5f);
    }
    __syncthreads();
    const float mean = s_mean, rstd = s_rstd;

    for (int j = tid; j < NELEM; j += 256) {
        int s = j >> 6, i = j & 63;
        size_t off = base + (size_t)s * DD + i;
        int c = h * HD + i;
        g_xr[off] = (g_wkv[off] - mean) * rstd * gamma[c] + beta[c];
    }
}

// ---------------------------------------------------------------------------
// Launch
// ---------------------------------------------------------------------------
extern "C" void kernel_launch(void* const* d_in, const int* in_sizes, int n_in,
                              void* d_out, int out_size) {
    const float* x     = (const float*)d_in[0];
    const float* tmr   = (const float*)d_in[1];
    const float* tmk   = (const float*)d_in[2];
    const float* tmv   = (const float*)d_in[3];
    const float* Wr    = (const float*)d_in[4];
    const float* Wk    = (const float*)d_in[5];
    const float* Wv    = (const float*)d_in[6];
    const float* Wo    = (const float*)d_in[7];
    const float* td    = (const float*)d_in[8];
    const float* tf    = (const float*)d_in[9];
    const float* gamma = (const float*)d_in[10];
    const float* beta  = (const float*)d_in[11];
    float* out = (float*)d_out;

    float *xr, *xk, *xv, *r, *k, *v;
    cudaGetSymbolAddress((void**)&xr, g_xr);
    cudaGetSymbolAddress((void**)&xk, g_xk);
    cudaGetSymbolAddress((void**)&xv, g_xv);
    cudaGetSymbolAddress((void**)&r,  g_r);
    cudaGetSymbolAddress((void**)&k,  g_k);
    cudaGetSymbolAddress((void**)&v,  g_v);

    // 1. token shift + mixing
    mix_kernel<<<(ELEMS / 4 + 255) / 256, 256>>>(x, tmr, tmk, tmv);

    // 2. r/k/v projections
    dim3 gg(DD / 64, MTOT / 128);
    gemm128x64<<<gg, 256>>>(xr, Wr, r, MTOT, DD, DD);
    gemm128x64<<<gg, 256>>>(xk, Wk, k, MTOT, DD, DD);
    gemm128x64<<<gg, 256>>>(xv, Wv, v, MTOT, DD, DD);

    // 3. serial WKV recurrence
    wkv_kernel<<<32, 128>>>(td, tf);

    // 4. sigmoid gate + group norm (normed -> g_xr, reused)
    gn_kernel<<<BB * HH, 256>>>(gamma, beta);

    // 5. output projection
    gemm128x64<<<gg, 256>>>(xr, Wo, out, MTOT, DD, DD);
}

// round 2
// speedup vs baseline: 1.7869x; 1.7869x over previous
#include <cuda_runtime.h>
#include <math.h>

// Problem constants (fixed shapes per reference)
#define BB 4
#define SS 2048
#define DD 1024
#define HH 16
#define HD 64
#define MTOT (BB * SS)          // 8192 rows
#define ELEMS (BB * SS * DD)    // 8,388,608

#define NSEG 16
#define SEGL (SS / NSEG)        // 128
#define NC (BB * DD)            // 4096 channels
#define GSLICE 32

// ---------------------------------------------------------------------------
// Scratch (allocation-free: __device__ globals)
// ---------------------------------------------------------------------------
__device__ float g_xr[ELEMS];   // mixed r-input; later reused for normed output
__device__ float g_xk[ELEMS];
__device__ float g_xv[ELEMS];
__device__ float g_r[ELEMS];
__device__ float g_k[ELEMS];
__device__ float g_v[ELEMS];
__device__ float g_wkv[ELEMS];  // wkv; later overwritten with sigmoid(r)*wkv

// WKV scan scratch
__device__ float g_bs[NSEG * NC];
__device__ float g_bin[NSEG * NC];
__device__ float g_Cc[NSEG * NC];
__device__ float g_lP[NSEG * NC];
__device__ float g_ain[NSEG * NC];

// GroupNorm scratch
__device__ float g_psum[BB * HH * GSLICE];
__device__ float g_psq[BB * HH * GSLICE];
__device__ float g_mean[BB * HH];
__device__ float g_rstd[BB * HH];

// ---------------------------------------------------------------------------
// Kernel 1: token shift + time mixing -> xr, xk, xv  (float4 vectorized)
// ---------------------------------------------------------------------------
__global__ void mix_kernel(const float* __restrict__ x,
                           const float* __restrict__ tmr,
                           const float* __restrict__ tmk,
                           const float* __restrict__ tmv) {
    int idx = blockIdx.x * blockDim.x + threadIdx.x;   // float4 index
    const int TOT4 = ELEMS / 4;
    if (idx >= TOT4) return;
    const int D4 = DD / 4;
    int d4 = idx % D4;
    int bs = idx / D4;
    int s  = bs % SS;

    const float4* x4 = (const float4*)x;
    float4 xv_ = x4[idx];
    float4 sh  = (s > 0) ? x4[idx - D4] : make_float4(0.f, 0.f, 0.f, 0.f);
    float4 mr = ((const float4*)tmr)[d4];
    float4 mk = ((const float4*)tmk)[d4];
    float4 mv = ((const float4*)tmv)[d4];

    float4 orr, okk, ovv;
    orr.x = xv_.x * mr.x + sh.x * (1.f - mr.x);
    orr.y = xv_.y * mr.y + sh.y * (1.f - mr.y);
    orr.z = xv_.z * mr.z + sh.z * (1.f - mr.z);
    orr.w = xv_.w * mr.w + sh.w * (1.f - mr.w);
    okk.x = xv_.x * mk.x + sh.x * (1.f - mk.x);
    okk.y = xv_.y * mk.y + sh.y * (1.f - mk.y);
    okk.z = xv_.z * mk.z + sh.z * (1.f - mk.z);
    okk.w = xv_.w * mk.w + sh.w * (1.f - mk.w);
    ovv.x = xv_.x * mv.x + sh.x * (1.f - mv.x);
    ovv.y = xv_.y * mv.y + sh.y * (1.f - mv.y);
    ovv.z = xv_.z * mv.z + sh.z * (1.f - mv.z);
    ovv.w = xv_.w * mv.w + sh.w * (1.f - mv.w);

    ((float4*)g_xr)[idx] = orr;
    ((float4*)g_xk)[idx] = okk;
    ((float4*)g_xv)[idx] = ovv;
}

// ---------------------------------------------------------------------------
// Kernel 2: fp32 GEMM  C[M,N] = A[M,K] * B[N,K]^T
// 128x128 tile, 256 threads, 8x8 microtile, smem double-buffered (1 sync/iter)
// ---------------------------------------------------------------------------
__global__ __launch_bounds__(256, 2)
void gemm128(const float* __restrict__ A, const float* __restrict__ Bm,
             float* __restrict__ C, int M, int N, int K) {
    __shared__ float As[2][16][132];
    __shared__ float Bs[2][16][132];

    const int tid = threadIdx.x;
    const int tx = tid & 15;       // 0..15 -> 8 cols each
    const int ty = tid >> 4;       // 0..15 -> 8 rows each
    const int bm = blockIdx.y * 128;
    const int bn = blockIdx.x * 128;

    const float* Ab = A + (size_t)bm * K;
    const float* Bb = Bm + (size_t)bn * K;

    const int lrow = tid >> 2;          // 0..63
    const int lcg  = (tid & 3) << 2;    // 0,4,8,12

    float acc[8][8];
#pragma unroll
    for (int i = 0; i < 8; i++)
#pragma unroll
        for (int j = 0; j < 8; j++) acc[i][j] = 0.f;

    // preload tile 0 -> regs -> smem buf 0
    float4 pa0 = *(const float4*)(Ab + (size_t)lrow * K + lcg);
    float4 pa1 = *(const float4*)(Ab + (size_t)(lrow + 64) * K + lcg);
    float4 pb0 = *(const float4*)(Bb + (size_t)lrow * K + lcg);
    float4 pb1 = *(const float4*)(Bb + (size_t)(lrow + 64) * K + lcg);

    int p = 0;
    As[p][lcg + 0][lrow] = pa0.x; As[p][lcg + 1][lrow] = pa0.y;
    As[p][lcg + 2][lrow] = pa0.z; As[p][lcg + 3][lrow] = pa0.w;
    As[p][lcg + 0][lrow + 64] = pa1.x; As[p][lcg + 1][lrow + 64] = pa1.y;
    As[p][lcg + 2][lrow + 64] = pa1.z; As[p][lcg + 3][lrow + 64] = pa1.w;
    Bs[p][lcg + 0][lrow] = pb0.x; Bs[p][lcg + 1][lrow] = pb0.y;
    Bs[p][lcg + 2][lrow] = pb0.z; Bs[p][lcg + 3][lrow] = pb0.w;
    Bs[p][lcg + 0][lrow + 64] = pb1.x; Bs[p][lcg + 1][lrow + 64] = pb1.y;
    Bs[p][lcg + 2][lrow + 64] = pb1.z; Bs[p][lcg + 3][lrow + 64] = pb1.w;
    __syncthreads();

    for (int k0 = 16; k0 <= K; k0 += 16) {
        if (k0 < K) {
            pa0 = *(const float4*)(Ab + (size_t)lrow * K + k0 + lcg);
            pa1 = *(const float4*)(Ab + (size_t)(lrow + 64) * K + k0 + lcg);
            pb0 = *(const float4*)(Bb + (size_t)lrow * K + k0 + lcg);
            pb1 = *(const float4*)(Bb + (size_t)(lrow + 64) * K + k0 + lcg);
        }
#pragma unroll
        for (int kk = 0; kk < 16; kk++) {
            float4 a0 = *(const float4*)&As[p][kk][ty * 8];
            float4 a1 = *(const float4*)&As[p][kk][ty * 8 + 4];
            float4 b0 = *(const float4*)&Bs[p][kk][tx * 8];
            float4 b1 = *(const float4*)&Bs[p][kk][tx * 8 + 4];
            float a[8] = {a0.x, a0.y, a0.z, a0.w, a1.x, a1.y, a1.z, a1.w};
            float b[8] = {b0.x, b0.y, b0.z, b0.w, b1.x, b1.y, b1.z, b1.w};
#pragma unroll
            for (int i = 0; i < 8; i++)
#pragma unroll
                for (int j = 0; j < 8; j++) acc[i][j] = fmaf(a[i], b[j], acc[i][j]);
        }
        if (k0 < K) {
            int q = p ^ 1;
            As[q][lcg + 0][lrow] = pa0.x; As[q][lcg + 1][lrow] = pa0.y;
            As[q][lcg + 2][lrow] = pa0.z; As[q][lcg + 3][lrow] = pa0.w;
            As[q][lcg + 0][lrow + 64] = pa1.x; As[q][lcg + 1][lrow + 64] = pa1.y;
            As[q][lcg + 2][lrow + 64] = pa1.z; As[q][lcg + 3][lrow + 64] = pa1.w;
            Bs[q][lcg + 0][lrow] = pb0.x; Bs[q][lcg + 1][lrow] = pb0.y;
            Bs[q][lcg + 2][lrow] = pb0.z; Bs[q][lcg + 3][lrow] = pb0.w;
            Bs[q][lcg + 0][lrow + 64] = pb1.x; Bs[q][lcg + 1][lrow + 64] = pb1.y;
            Bs[q][lcg + 2][lrow + 64] = pb1.z; Bs[q][lcg + 3][lrow + 64] = pb1.w;
            __syncthreads();
            p = q;
        }
    }

#pragma unroll
    for (int i = 0; i < 8; i++) {
        float4 o0, o1;
        o0.x = acc[i][0]; o0.y = acc[i][1]; o0.z = acc[i][2]; o0.w = acc[i][3];
        o1.x = acc[i][4]; o1.y = acc[i][5]; o1.z = acc[i][6]; o1.w = acc[i][7];
        float* cp = C + (size_t)(bm + ty * 8 + i) * N + bn + tx * 8;
        *(float4*)cp = o0;
        *(float4*)(cp + 4) = o1;
    }
}

// ---------------------------------------------------------------------------
// WKV segmented scan.
// b-state: D' = D*e^w + e^k  (log-space, stable) — independent of a.
// a-state: a' = alpha_t * a + beta_t (linear given true b sequence),
//          alpha_t = e^{b+w-p2} <= 1.
// ---------------------------------------------------------------------------

// P1: per-segment b summary from scratch
__global__ void wkv_p1(const float* __restrict__ td) {
    int gid = blockIdx.x * blockDim.x + threadIdx.x;
    if (gid >= NSEG * NC) return;
    int c = gid % DD;
    int r = gid / DD;
    int b = r % BB;
    int seg = r / BB;
    float w = -__expf(td[c]);
    const float* kp = g_k + ((size_t)b * SS + (size_t)seg * SEGL) * DD + c;
    float bb = -1e38f;
#pragma unroll 4
    for (int t = 0; t < SEGL; t++) {
        float kt = kp[(size_t)t * DD];
        float ww = bb + w;
        float p2 = fmaxf(ww, kt);
        float e1 = __expf(ww - p2);
        float e2 = __expf(kt - p2);
        bb = p2 + __logf(e1 + e2 + 1e-8f);
    }
    g_bs[seg * NC + b * DD + c] = bb;
}

// P2: sequential combine of b across segments (per channel)
__global__ void wkv_p2(const float* __restrict__ td) {
    int ch = blockIdx.x * blockDim.x + threadIdx.x;
    if (ch >= NC) return;
    int c = ch % DD;
    float w = -__expf(td[c]);
    float Lw = (float)SEGL * w;
    float bin = -1e38f;
#pragma unroll
    for (int s = 0; s < NSEG; s++) {
        g_bin[s * NC + ch] = bin;
        float x = bin + Lw;
        float y = g_bs[s * NC + ch];
        float p = fmaxf(x, y);
        bin = p + __logf(__expf(x - p) + __expf(y - p));
    }
}

// P3: per-segment a-contribution C and log(prod alpha), using true b_in
__global__ void wkv_p3(const float* __restrict__ td) {
    int gid = blockIdx.x * blockDim.x + threadIdx.x;
    if (gid >= NSEG * NC) return;
    int c = gid % DD;
    int r = gid / DD;
    int b = r % BB;
    int seg = r / BB;
    float w = -__expf(td[c]);
    const float* kp = g_k + ((size_t)b * SS + (size_t)seg * SEGL) * DD + c;
    const float* vp = g_v + ((size_t)b * SS + (size_t)seg * SEGL) * DD + c;
    int sidx = seg * NC + b * DD + c;
    float bb = g_bin[sidx];
    float aa = 0.f, lP = 0.f;
#pragma unroll 4
    for (int t = 0; t < SEGL; t++) {
        float kt = kp[(size_t)t * DD];
        float vt = vp[(size_t)t * DD];
        float ww = bb + w;
        float p2 = fmaxf(ww, kt);
        lP += ww - p2;
        float e1b = __expf(ww - p2);
        float e2b = __expf(kt - p2);
        aa = e1b * aa + e2b * vt;
        bb = p2 + __logf(e1b + e2b + 1e-8f);
    }
    g_Cc[sidx] = aa;
    g_lP[sidx] = lP;
}

// P4: sequential combine of a across segments (per channel)
__global__ void wkv_p4() {
    int ch = blockIdx.x * blockDim.x + threadIdx.x;
    if (ch >= NC) return;
    float ain = 0.f;
#pragma unroll
    for (int s = 0; s < NSEG; s++) {
        g_ain[s * NC + ch] = ain;
        ain = __expf(g_lP[s * NC + ch]) * ain + g_Cc[s * NC + ch];
    }
}

// P5: replay within segment from true (a_in, b_in), emit outputs
__global__ void wkv_p5(const float* __restrict__ td, const float* __restrict__ tf) {
    int gid = blockIdx.x * blockDim.x + threadIdx.x;
    if (gid >= NSEG * NC) return;
    int c = gid % DD;
    int r = gid / DD;
    int b = r % BB;
    int seg = r / BB;
    float w = -__expf(td[c]);
    float u = tf[c];
    size_t off0 = ((size_t)b * SS + (size_t)seg * SEGL) * DD + c;
    const float* kp = g_k + off0;
    const float* vp = g_v + off0;
    float* op = g_wkv + off0;
    int sidx = seg * NC + b * DD + c;
    float aa = g_ain[sidx];
    float bb = g_bin[sidx];
#pragma unroll 2
    for (int t = 0; t < SEGL; t++) {
        float kt = kp[(size_t)t * DD];
        float vt = vp[(size_t)t * DD];
        float wk = kt + u;
        float p = fmaxf(bb, wk);
        float e1 = __expf(bb - p);
        float e2 = __expf(wk - p);
        op[(size_t)t * DD] = (e1 * aa + e2 * vt) / (e1 + e2 + 1e-8f);
        float ww = bb + w;
        float p2 = fmaxf(ww, kt);
        float e1b = __expf(ww - p2);
        float e2b = __expf(kt - p2);
        aa = e1b * aa + e2b * vt;
        bb = p2 + __logf(e1b + e2b + 1e-8f);
    }
}

// ---------------------------------------------------------------------------
// GroupNorm, 3 phases (deterministic, fully parallel)
// ---------------------------------------------------------------------------
__global__ __launch_bounds__(256)
void gn_sum() {
    const int grp = blockIdx.y;        // 0..63  (b*HH + h)
    const int slice = blockIdx.x;      // 0..GSLICE-1
    const int b = grp / HH;
    const int h = grp % HH;
    const size_t base = (size_t)b * SS * DD + (size_t)h * HD;
    const int tid = threadIdx.x;
    const int SROWS = SS / GSLICE;     // 64 seq rows per slice

    float sum = 0.f, sq = 0.f;
    for (int j = tid; j < SROWS * HD; j += 256) {
        int s = slice * SROWS + (j >> 6);
        int i = j & 63;
        size_t off = base + (size_t)s * DD + i;
        float y = g_wkv[off] / (1.f + __expf(-g_r[off]));
        g_wkv[off] = y;
        sum += y;
        sq += y * y;
    }

    __shared__ float r1[256], r2[256];
    r1[tid] = sum; r2[tid] = sq;
    __syncthreads();
#pragma unroll
    for (int o = 128; o > 0; o >>= 1) {
        if (tid < o) { r1[tid] += r1[tid + o]; r2[tid] += r2[tid + o]; }
        __syncthreads();
    }
    if (tid == 0) {
        g_psum[grp * GSLICE + slice] = r1[0];
        g_psq[grp * GSLICE + slice] = r2[0];
    }
}

__global__ void gn_mid() {
    int g = threadIdx.x;
    if (g >= BB * HH) return;
    float s = 0.f, q = 0.f;
#pragma unroll
    for (int i = 0; i < GSLICE; i++) {
        s += g_psum[g * GSLICE + i];
        q += g_psq[g * GSLICE + i];
    }
    const float inv = 1.f / (float)(SS * HD);
    float mean = s * inv;
    float var = q * inv - mean * mean;
    g_mean[g] = mean;
    g_rstd[g] = rsqrtf(var + 1e-5f);
}

__global__ void gn_norm(const float* __restrict__ gamma,
                        const float* __restrict__ beta) {
    int idx = blockIdx.x * blockDim.x + threadIdx.x;   // float4 index
    const int TOT4 = ELEMS / 4;
    if (idx >= TOT4) return;
    const int D4 = DD / 4;
    int d4 = idx % D4;
    int bs = idx / D4;
    int b = bs / SS;
    int c0 = d4 * 4;
    int h = c0 / HD;
    int grp = b * HH + h;
    float mean = g_mean[grp];
    float rstd = g_rstd[grp];
    float4 y = ((const float4*)g_wkv)[idx];
    float4 ga = ((const float4*)gamma)[d4];
    float4 be = ((const float4*)beta)[d4];
    float4 o;
    o.x = (y.x - mean) * rstd * ga.x + be.x;
    o.y = (y.y - mean) * rstd * ga.y + be.y;
    o.z = (y.z - mean) * rstd * ga.z + be.z;
    o.w = (y.w - mean) * rstd * ga.w + be.w;
    ((float4*)g_xr)[idx] = o;
}

// ---------------------------------------------------------------------------
// Launch
// ---------------------------------------------------------------------------
extern "C" void kernel_launch(void* const* d_in, const int* in_sizes, int n_in,
                              void* d_out, int out_size) {
    const float* x     = (const float*)d_in[0];
    const float* tmr   = (const float*)d_in[1];
    const float* tmk   = (const float*)d_in[2];
    const float* tmv   = (const float*)d_in[3];
    const float* Wr    = (const float*)d_in[4];
    const float* Wk    = (const float*)d_in[5];
    const float* Wv    = (const float*)d_in[6];
    const float* Wo    = (const float*)d_in[7];
    const float* td    = (const float*)d_in[8];
    const float* tf    = (const float*)d_in[9];
    const float* gamma = (const float*)d_in[10];
    const float* beta  = (const float*)d_in[11];
    float* out = (float*)d_out;

    float *xr, *xk, *xv, *r, *k, *v;
    cudaGetSymbolAddress((void**)&xr, g_xr);
    cudaGetSymbolAddress((void**)&xk, g_xk);
    cudaGetSymbolAddress((void**)&xv, g_xv);
    cudaGetSymbolAddress((void**)&r,  g_r);
    cudaGetSymbolAddress((void**)&k,  g_k);
    cudaGetSymbolAddress((void**)&v,  g_v);

    // 1. token shift + mixing
    mix_kernel<<<(ELEMS / 4 + 255) / 256, 256>>>(x, tmr, tmk, tmv);

    // 2. r/k/v projections (128x128 tiles)
    dim3 gg(DD / 128, MTOT / 128);
    gemm128<<<gg, 256>>>(xr, Wr, r, MTOT, DD, DD);
    gemm128<<<gg, 256>>>(xk, Wk, k, MTOT, DD, DD);
    gemm128<<<gg, 256>>>(xv, Wv, v, MTOT, DD, DD);

    // 3. segmented WKV scan
    wkv_p1<<<(NSEG * NC + 255) / 256, 256>>>(td);
    wkv_p2<<<(NC + 255) / 256, 256>>>(td);
    wkv_p3<<<(NSEG * NC + 255) / 256, 256>>>(td);
    wkv_p4<<<(NC + 255) / 256, 256>>>();
    wkv_p5<<<(NSEG * NC + 255) / 256, 256>>>(td, tf);

    // 4. sigmoid gate + group norm
    dim3 gns(GSLICE, BB * HH);
    gn_sum<<<gns, 256>>>();
    gn_mid<<<1, 64>>>();
    gn_norm<<<(ELEMS / 4 + 255) / 256, 256>>>(gamma, beta);

    // 5. output projection
    gemm128<<<gg, 256>>>(xr, Wo, out, MTOT, DD, DD);
}

// round 4
// speedup vs baseline: 3.5648x; 1.9950x over previous
#include <cuda_runtime.h>
#include <cuda_bf16.h>
#include <math.h>
#include <cstdint>

// Problem constants
#define BB 4
#define SS 2048
#define DD 1024
#define HH 16
#define HD 64
#define MTOT (BB * SS)          // 8192
#define ELEMS (BB * SS * DD)    // 8,388,608
#define KDIM 1024

#define NSEG 16
#define SEGL (SS / NSEG)
#define NC (BB * DD)
#define GSLICE 32

// ---------------------------------------------------------------------------
// Scratch (allocation-free: __device__ globals)
// ---------------------------------------------------------------------------
__device__ float g_r[ELEMS];
__device__ float g_k[ELEMS];
__device__ float g_v[ELEMS];
__device__ float g_wkv[ELEMS];

// bf16 hi/lo split activations
__device__ __nv_bfloat16 g_xrh[ELEMS];
__device__ __nv_bfloat16 g_xrl[ELEMS];
__device__ __nv_bfloat16 g_xkh[ELEMS];
__device__ __nv_bfloat16 g_xkl[ELEMS];
__device__ __nv_bfloat16 g_xvh[ELEMS];
__device__ __nv_bfloat16 g_xvl[ELEMS];

// bf16 hi/lo split weights
__device__ __nv_bfloat16 g_Wrh[DD * DD];
__device__ __nv_bfloat16 g_Wrl[DD * DD];
__device__ __nv_bfloat16 g_Wkh[DD * DD];
__device__ __nv_bfloat16 g_Wkl[DD * DD];
__device__ __nv_bfloat16 g_Wvh[DD * DD];
__device__ __nv_bfloat16 g_Wvl[DD * DD];
__device__ __nv_bfloat16 g_Woh[DD * DD];
__device__ __nv_bfloat16 g_Wol[DD * DD];

// WKV scan scratch
__device__ float g_bs[NSEG * NC];
__device__ float g_bin[NSEG * NC];
__device__ float g_Cc[NSEG * NC];
__device__ float g_lP[NSEG * NC];
__device__ float g_ain[NSEG * NC];

// GroupNorm scratch
__device__ float g_psum[BB * HH * GSLICE];
__device__ float g_psq[BB * HH * GSLICE];
__device__ float g_mean[BB * HH];
__device__ float g_rstd[BB * HH];

// ---------------------------------------------------------------------------
// helpers
// ---------------------------------------------------------------------------
__device__ __forceinline__ uint32_t smem_u32(const void* p) {
    uint32_t a;
    asm("{ .reg .u64 t; cvta.to.shared.u64 t, %1; cvt.u32.u64 %0, t; }"
        : "=r"(a) : "l"(p));
    return a;
}

__device__ __forceinline__ void cpa16(uint32_t s, const void* g) {
    asm volatile("cp.async.cg.shared.global [%0], [%1], 16;\n" :: "r"(s), "l"(g));
}
__device__ __forceinline__ void cpa_commit() {
    asm volatile("cp.async.commit_group;\n" ::: "memory");
}
template <int N>
__device__ __forceinline__ void cpa_wait() {
    asm volatile("cp.async.wait_group %0;\n" :: "n"(N) : "memory");
}

__device__ __forceinline__ void mma_bf16(float* c, const uint32_t* a,
                                         const uint32_t* b) {
    asm volatile(
        "mma.sync.aligned.m16n8k16.row.col.f32.bf16.bf16.f32 "
        "{%0,%1,%2,%3}, {%4,%5,%6,%7}, {%8,%9}, {%0,%1,%2,%3};\n"
        : "+f"(c[0]), "+f"(c[1]), "+f"(c[2]), "+f"(c[3])
        : "r"(a[0]), "r"(a[1]), "r"(a[2]), "r"(a[3]), "r"(b[0]), "r"(b[1]));
}

// split helper: hi = bf16_rn(x), lo = bf16_rn(x - hi)
__device__ __forceinline__ void split2(float a, float b, uint32_t& hi, uint32_t& lo) {
    __nv_bfloat16 ha = __float2bfloat16(a);
    __nv_bfloat16 hb = __float2bfloat16(b);
    __nv_bfloat16 la = __float2bfloat16(a - __bfloat162float(ha));
    __nv_bfloat16 lb = __float2bfloat16(b - __bfloat162float(hb));
    __nv_bfloat162 h = __nv_bfloat162(ha, hb);
    __nv_bfloat162 l = __nv_bfloat162(la, lb);
    hi = *(uint32_t*)&h;
    lo = *(uint32_t*)&l;
}

// ---------------------------------------------------------------------------
// Kernel: split a weight matrix into bf16 hi/lo
// ---------------------------------------------------------------------------
__global__ void split_w(const float* __restrict__ W,
                        __nv_bfloat16* __restrict__ H,
                        __nv_bfloat16* __restrict__ L) {
    int idx = blockIdx.x * blockDim.x + threadIdx.x;
    if (idx >= DD * DD / 4) return;
    float4 a = ((const float4*)W)[idx];
    uint2 h, l;
    split2(a.x, a.y, h.x, l.x);
    split2(a.z, a.w, h.y, l.y);
    ((uint2*)H)[idx] = h;
    ((uint2*)L)[idx] = l;
}

// ---------------------------------------------------------------------------
// Kernel: token shift + mixing -> bf16 hi/lo of xr, xk, xv
// ---------------------------------------------------------------------------
__global__ void mix_kernel(const float* __restrict__ x,
                           const float* __restrict__ tmr,
                           const float* __restrict__ tmk,
                           const float* __restrict__ tmv) {
    int idx = blockIdx.x * blockDim.x + threadIdx.x;
    const int TOT4 = ELEMS / 4;
    if (idx >= TOT4) return;
    const int D4 = DD / 4;
    int d4 = idx % D4;
    int bs = idx / D4;
    int s = bs % SS;

    const float4* x4 = (const float4*)x;
    float4 xv_ = x4[idx];
    float4 sh = (s > 0) ? x4[idx - D4] : make_float4(0.f, 0.f, 0.f, 0.f);
    float4 mr = ((const float4*)tmr)[d4];
    float4 mk = ((const float4*)tmk)[d4];
    float4 mv = ((const float4*)tmv)[d4];

    float4 orr, okk, ovv;
    orr.x = xv_.x * mr.x + sh.x * (1.f - mr.x);
    orr.y = xv_.y * mr.y + sh.y * (1.f - mr.y);
    orr.z = xv_.z * mr.z + sh.z * (1.f - mr.z);
    orr.w = xv_.w * mr.w + sh.w * (1.f - mr.w);
    okk.x = xv_.x * mk.x + sh.x * (1.f - mk.x);
    okk.y = xv_.y * mk.y + sh.y * (1.f - mk.y);
    okk.z = xv_.z * mk.z + sh.z * (1.f - mk.z);
    okk.w = xv_.w * mk.w + sh.w * (1.f - mk.w);
    ovv.x = xv_.x * mv.x + sh.x * (1.f - mv.x);
    ovv.y = xv_.y * mv.y + sh.y * (1.f - mv.y);
    ovv.z = xv_.z * mv.z + sh.z * (1.f - mv.z);
    ovv.w = xv_.w * mv.w + sh.w * (1.f - mv.w);

    uint2 h, l;
    split2(orr.x, orr.y, h.x, l.x); split2(orr.z, orr.w, h.y, l.y);
    ((uint2*)g_xrh)[idx] = h; ((uint2*)g_xrl)[idx] = l;
    split2(okk.x, okk.y, h.x, l.x); split2(okk.z, okk.w, h.y, l.y);
    ((uint2*)g_xkh)[idx] = h; ((uint2*)g_xkl)[idx] = l;
    split2(ovv.x, ovv.y, h.x, l.x); split2(ovv.z, ovv.w, h.y, l.y);
    ((uint2*)g_xvh)[idx] = h; ((uint2*)g_xvl)[idx] = l;
}

// ---------------------------------------------------------------------------
// bf16-split tensor-core GEMM:
//   C[8192,1024] = (Ah+Al)[8192,1024] * (Bh+Bl)[1024,1024]^T  (fp32 out)
// 128x128 CTA tile, 8 warps (2x4), warp tile 64x32, k-chunk 32,
// cp.async double buffer. 3 mma products: ah*bh + ah*bl + al*bh.
// ---------------------------------------------------------------------------
#define WR 20                       // 32-bit words per smem row (16 data + 4 pad)
#define PART_WORDS (128 * WR)       // 2560 words per tile part
#define BUF_WORDS (4 * PART_WORDS)  // Ahi, Alo, Bhi, Blo
#define GSM_BYTES (2 * BUF_WORDS * 4)  // 81920

__global__ __launch_bounds__(256, 2)
void gemm_bf16x2(const __nv_bfloat16* __restrict__ Ah,
                 const __nv_bfloat16* __restrict__ Al,
                 const __nv_bfloat16* __restrict__ Bh,
                 const __nv_bfloat16* __restrict__ Bl,
                 float* __restrict__ C) {
    extern __shared__ uint32_t sm[];
    const uint32_t smb = smem_u32(sm);
    const int tid = threadIdx.x;
    const int lane = tid & 31;
    const int wid = tid >> 5;
    const int wm = wid >> 2;       // 0..1
    const int wn = wid & 3;        // 0..3
    const int bm = blockIdx.y * 128;
    const int bn = blockIdx.x * 128;

    const __nv_bfloat16* src[4] = {
        Ah + (size_t)bm * KDIM, Al + (size_t)bm * KDIM,
        Bh + (size_t)bn * KDIM, Bl + (size_t)bn * KDIM};

    float c[4][4][4];
#pragma unroll
    for (int i = 0; i < 4; i++)
#pragma unroll
        for (int j = 0; j < 4; j++)
#pragma unroll
            for (int q = 0; q < 4; q++) c[i][j][q] = 0.f;

    auto load_stage = [&](int buf, int k0) {
#pragma unroll
        for (int i = 0; i < 8; i++) {
            int id = tid + i * 256;
            int part = id >> 9;
            int pid = id & 511;
            int row = pid >> 2;
            int wc = pid & 3;
            uint32_t saddr =
                smb + (uint32_t)(buf * BUF_WORDS + part * PART_WORDS +
                                 row * WR + wc * 4) * 4u;
            cpa16(saddr, src[part] + (size_t)row * KDIM + k0 + wc * 8);
        }
    };

    load_stage(0, 0);
    cpa_commit();

#pragma unroll 1
    for (int it = 0; it < 32; ++it) {
        if (it + 1 < 32) {
            load_stage((it + 1) & 1, (it + 1) * 32);
            cpa_commit();
            cpa_wait<1>();
        } else {
            cpa_wait<0>();
        }
        __syncthreads();

        const uint32_t* Sah = sm + (it & 1) * BUF_WORDS;
        const uint32_t* Sal = Sah + PART_WORDS;
        const uint32_t* Sbh = Sah + 2 * PART_WORDS;
        const uint32_t* Sbl = Sah + 3 * PART_WORDS;

#pragma unroll
        for (int ks = 0; ks < 2; ks++) {
            const int c0 = (lane & 3) + ks * 8;
            uint32_t bh[4][2], bl[4][2];
#pragma unroll
            for (int ni = 0; ni < 4; ni++) {
                int n = wn * 32 + ni * 8 + (lane >> 2);
                bh[ni][0] = Sbh[n * WR + c0];
                bh[ni][1] = Sbh[n * WR + c0 + 4];
                bl[ni][0] = Sbl[n * WR + c0];
                bl[ni][1] = Sbl[n * WR + c0 + 4];
            }
#pragma unroll
            for (int mi = 0; mi < 4; mi++) {
                int r = wm * 64 + mi * 16 + (lane >> 2);
                uint32_t ah[4], al[4];
                ah[0] = Sah[r * WR + c0];
                ah[1] = Sah[(r + 8) * WR + c0];
                ah[2] = Sah[r * WR + c0 + 4];
                ah[3] = Sah[(r + 8) * WR + c0 + 4];
                al[0] = Sal[r * WR + c0];
                al[1] = Sal[(r + 8) * WR + c0];
                al[2] = Sal[r * WR + c0 + 4];
                al[3] = Sal[(r + 8) * WR + c0 + 4];
#pragma unroll
                for (int ni = 0; ni < 4; ni++) {
                    mma_bf16(c[mi][ni], ah, bh[ni]);
                    mma_bf16(c[mi][ni], ah, bl[ni]);
                    mma_bf16(c[mi][ni], al, bh[ni]);
                }
            }
        }
        __syncthreads();
    }

    // writeback
#pragma unroll
    for (int mi = 0; mi < 4; mi++) {
        int r0 = bm + wm * 64 + mi * 16 + (lane >> 2);
#pragma unroll
        for (int ni = 0; ni < 4; ni++) {
            int col = bn + wn * 32 + ni * 8 + 2 * (lane & 3);
            float2 v01 = make_float2(c[mi][ni][0], c[mi][ni][1]);
            float2 v23 = make_float2(c[mi][ni][2], c[mi][ni][3]);
            *(float2*)(C + (size_t)r0 * DD + col) = v01;
            *(float2*)(C + (size_t)(r0 + 8) * DD + col) = v23;
        }
    }
}

// ---------------------------------------------------------------------------
// WKV segmented scan (validated in round 2)
// ---------------------------------------------------------------------------
__global__ void wkv_p1(const float* __restrict__ td) {
    int gid = blockIdx.x * blockDim.x + threadIdx.x;
    if (gid >= NSEG * NC) return;
    int c = gid % DD;
    int r = gid / DD;
    int b = r % BB;
    int seg = r / BB;
    float w = -__expf(td[c]);
    const float* kp = g_k + ((size_t)b * SS + (size_t)seg * SEGL) * DD + c;
    float bb = -1e38f;
#pragma unroll 4
    for (int t = 0; t < SEGL; t++) {
        float kt = kp[(size_t)t * DD];
        float ww = bb + w;
        float p2 = fmaxf(ww, kt);
        float e1 = __expf(ww - p2);
        float e2 = __expf(kt - p2);
        bb = p2 + __logf(e1 + e2 + 1e-8f);
    }
    g_bs[seg * NC + b * DD + c] = bb;
}

__global__ void wkv_p2(const float* __restrict__ td) {
    int ch = blockIdx.x * blockDim.x + threadIdx.x;
    if (ch >= NC) return;
    int c = ch % DD;
    float w = -__expf(td[c]);
    float Lw = (float)SEGL * w;
    float bin = -1e38f;
#pragma unroll
    for (int s = 0; s < NSEG; s++) {
        g_bin[s * NC + ch] = bin;
        float x = bin + Lw;
        float y = g_bs[s * NC + ch];
        float p = fmaxf(x, y);
        bin = p + __logf(__expf(x - p) + __expf(y - p));
    }
}

__global__ void wkv_p3(const float* __restrict__ td) {
    int gid = blockIdx.x * blockDim.x + threadIdx.x;
    if (gid >= NSEG * NC) return;
    int c = gid % DD;
    int r = gid / DD;
    int b = r % BB;
    int seg = r / BB;
    float w = -__expf(td[c]);
    const float* kp = g_k + ((size_t)b * SS + (size_t)seg * SEGL) * DD + c;
    const float* vp = g_v + ((size_t)b * SS + (size_t)seg * SEGL) * DD + c;
    int sidx = seg * NC + b * DD + c;
    float bb = g_bin[sidx];
    float aa = 0.f, lP = 0.f;
#pragma unroll 4
    for (int t = 0; t < SEGL; t++) {
        float kt = kp[(size_t)t * DD];
        float vt = vp[(size_t)t * DD];
        float ww = bb + w;
        float p2 = fmaxf(ww, kt);
        lP += ww - p2;
        float e1b = __expf(ww - p2);
        float e2b = __expf(kt - p2);
        aa = e1b * aa + e2b * vt;
        bb = p2 + __logf(e1b + e2b + 1e-8f);
    }
    g_Cc[sidx] = aa;
    g_lP[sidx] = lP;
}

__global__ void wkv_p4() {
    int ch = blockIdx.x * blockDim.x + threadIdx.x;
    if (ch >= NC) return;
    float ain = 0.f;
#pragma unroll
    for (int s = 0; s < NSEG; s++) {
        g_ain[s * NC + ch] = ain;
        ain = __expf(g_lP[s * NC + ch]) * ain + g_Cc[s * NC + ch];
    }
}

__global__ void wkv_p5(const float* __restrict__ td, const float* __restrict__ tf) {
    int gid = blockIdx.x * blockDim.x + threadIdx.x;
    if (gid >= NSEG * NC) return;
    int c = gid % DD;
    int r = gid / DD;
    int b = r % BB;
    int seg = r / BB;
    float w = -__expf(td[c]);
    float u = tf[c];
    size_t off0 = ((size_t)b * SS + (size_t)seg * SEGL) * DD + c;
    const float* kp = g_k + off0;
    const float* vp = g_v + off0;
    float* op = g_wkv + off0;
    int sidx = seg * NC + b * DD + c;
    float aa = g_ain[sidx];
    float bb = g_bin[sidx];
#pragma unroll 2
    for (int t = 0; t < SEGL; t++) {
        float kt = kp[(size_t)t * DD];
        float vt = vp[(size_t)t * DD];
        float wk = kt + u;
        float p = fmaxf(bb, wk);
        float e1 = __expf(bb - p);
        float e2 = __expf(wk - p);
        op[(size_t)t * DD] = (e1 * aa + e2 * vt) / (e1 + e2 + 1e-8f);
        float ww = bb + w;
        float p2 = fmaxf(ww, kt);
        float e1b = __expf(ww - p2);
        float e2b = __expf(kt - p2);
        aa = e1b * aa + e2b * vt;
        bb = p2 + __logf(e1b + e2b + 1e-8f);
    }
}

// ---------------------------------------------------------------------------
// GroupNorm (3 phases); final normed output -> bf16 hi/lo (g_xrh/g_xrl reuse)
// ---------------------------------------------------------------------------
__global__ __launch_bounds__(256)
void gn_sum() {
    const int grp = blockIdx.y;
    const int slice = blockIdx.x;
    const int b = grp / HH;
    const int h = grp % HH;
    const size_t base = (size_t)b * SS * DD + (size_t)h * HD;
    const int tid = threadIdx.x;
    const int SROWS = SS / GSLICE;

    float sum = 0.f, sq = 0.f;
    for (int j = tid; j < SROWS * HD; j += 256) {
        int s = slice * SROWS + (j >> 6);
        int i = j & 63;
        size_t off = base + (size_t)s * DD + i;
        float y = g_wkv[off] / (1.f + __expf(-g_r[off]));
        g_wkv[off] = y;
        sum += y;
        sq += y * y;
    }

    __shared__ float r1[256], r2[256];
    r1[tid] = sum; r2[tid] = sq;
    __syncthreads();
#pragma unroll
    for (int o = 128; o > 0; o >>= 1) {
        if (tid < o) { r1[tid] += r1[tid + o]; r2[tid] += r2[tid + o]; }
        __syncthreads();
    }
    if (tid == 0) {
        g_psum[grp * GSLICE + slice] = r1[0];
        g_psq[grp * GSLICE + slice] = r2[0];
    }
}

__global__ void gn_mid() {
    int g = threadIdx.x;
    if (g >= BB * HH) return;
    float s = 0.f, q = 0.f;
#pragma unroll
    for (int i = 0; i < GSLICE; i++) {
        s += g_psum[g * GSLICE + i];
        q += g_psq[g * GSLICE + i];
    }
    const float inv = 1.f / (float)(SS * HD);
    float mean = s * inv;
    float var = q * inv - mean * mean;
    g_mean[g] = mean;
    g_rstd[g] = rsqrtf(var + 1e-5f);
}

__global__ void gn_norm(const float* __restrict__ gamma,
                        const float* __restrict__ beta) {
    int idx = blockIdx.x * blockDim.x + threadIdx.x;
    const int TOT4 = ELEMS / 4;
    if (idx >= TOT4) return;
    const int D4 = DD / 4;
    int d4 = idx % D4;
    int bs = idx / D4;
    int b = bs / SS;
    int c0 = d4 * 4;
    int h = c0 / HD;
    int grp = b * HH + h;
    float mean = g_mean[grp];
    float rstd = g_rstd[grp];
    float4 y = ((const float4*)g_wkv)[idx];
    float4 ga = ((const float4*)gamma)[d4];
    float4 be = ((const float4*)beta)[d4];
    float4 o;
    o.x = (y.x - mean) * rstd * ga.x + be.x;
    o.y = (y.y - mean) * rstd * ga.y + be.y;
    o.z = (y.z - mean) * rstd * ga.z + be.z;
    o.w = (y.w - mean) * rstd * ga.w + be.w;
    uint2 hh, ll;
    split2(o.x, o.y, hh.x, ll.x);
    split2(o.z, o.w, hh.y, ll.y);
    ((uint2*)g_xrh)[idx] = hh;
    ((uint2*)g_xrl)[idx] = ll;
}

// ---------------------------------------------------------------------------
// Launch
// ---------------------------------------------------------------------------
extern "C" void kernel_launch(void* const* d_in, const int* in_sizes, int n_in,
                              void* d_out, int out_size) {
    const float* x     = (const float*)d_in[0];
    const float* tmr   = (const float*)d_in[1];
    const float* tmk   = (const float*)d_in[2];
    const float* tmv   = (const float*)d_in[3];
    const float* Wr    = (const float*)d_in[4];
    const float* Wk    = (const float*)d_in[5];
    const float* Wv    = (const float*)d_in[6];
    const float* Wo    = (const float*)d_in[7];
    const float* td    = (const float*)d_in[8];
    const float* tf    = (const float*)d_in[9];
    const float* gamma = (const float*)d_in[10];
    const float* beta  = (const float*)d_in[11];
    float* out = (float*)d_out;

    float *r, *k, *v;
    __nv_bfloat16 *xrh, *xrl, *xkh, *xkl, *xvh, *xvl;
    __nv_bfloat16 *wrh, *wrl, *wkh, *wkl, *wvh, *wvl, *woh, *wol;
    cudaGetSymbolAddress((void**)&r, g_r);
    cudaGetSymbolAddress((void**)&k, g_k);
    cudaGetSymbolAddress((void**)&v, g_v);
    cudaGetSymbolAddress((void**)&xrh, g_xrh);
    cudaGetSymbolAddress((void**)&xrl, g_xrl);
    cudaGetSymbolAddress((void**)&xkh, g_xkh);
    cudaGetSymbolAddress((void**)&xkl, g_xkl);
    cudaGetSymbolAddress((void**)&xvh, g_xvh);
    cudaGetSymbolAddress((void**)&xvl, g_xvl);
    cudaGetSymbolAddress((void**)&wrh, g_Wrh);
    cudaGetSymbolAddress((void**)&wrl, g_Wrl);
    cudaGetSymbolAddress((void**)&wkh, g_Wkh);
    cudaGetSymbolAddress((void**)&wkl, g_Wkl);
    cudaGetSymbolAddress((void**)&wvh, g_Wvh);
    cudaGetSymbolAddress((void**)&wvl, g_Wvl);
    cudaGetSymbolAddress((void**)&woh, g_Woh);
    cudaGetSymbolAddress((void**)&wol, g_Wol);

    cudaFuncSetAttribute(gemm_bf16x2,
                         cudaFuncAttributeMaxDynamicSharedMemorySize, GSM_BYTES);

    // 1. split weights + token-shift mixing
    const int WB = (DD * DD / 4 + 255) / 256;
    split_w<<<WB, 256>>>(Wr, wrh, wrl);
    split_w<<<WB, 256>>>(Wk, wkh, wkl);
    split_w<<<WB, 256>>>(Wv, wvh, wvl);
    split_w<<<WB, 256>>>(Wo, woh, wol);
    mix_kernel<<<(ELEMS / 4 + 255) / 256, 256>>>(x, tmr, tmk, tmv);

    // 2. r/k/v projections on tensor cores (bf16 split, 3-product)
    dim3 gg(DD / 128, MTOT / 128);
    gemm_bf16x2<<<gg, 256, GSM_BYTES>>>(xrh, xrl, wrh, wrl, r);
    gemm_bf16x2<<<gg, 256, GSM_BYTES>>>(xkh, xkl, wkh, wkl, k);
    gemm_bf16x2<<<gg, 256, GSM_BYTES>>>(xvh, xvl, wvh, wvl, v);

    // 3. segmented WKV scan
    wkv_p1<<<(NSEG * NC + 255) / 256, 256>>>(td);
    wkv_p2<<<(NC + 255) / 256, 256>>>(td);
    wkv_p3<<<(NSEG * NC + 255) / 256, 256>>>(td);
    wkv_p4<<<(NC + 255) / 256, 256>>>();
    wkv_p5<<<(NSEG * NC + 255) / 256, 256>>>(td, tf);

    // 4. sigmoid gate + group norm (split output into g_xrh/g_xrl)
    dim3 gns(GSLICE, BB * HH);
    gn_sum<<<gns, 256>>>();
    gn_mid<<<1, 64>>>();
    gn_norm<<<(ELEMS / 4 + 255) / 256, 256>>>(gamma, beta);

    // 5. output projection
    gemm_bf16x2<<<gg, 256, GSM_BYTES>>>(xrh, xrl, woh, wol, out);
}

// round 5
// speedup vs baseline: 3.6240x; 1.0166x over previous
#include <cuda_runtime.h>
#include <cuda_bf16.h>
#include <math.h>
#include <cstdint>

// Problem constants
#define BB 4
#define SS 2048
#define DD 1024
#define HH 16
#define HD 64
#define MTOT (BB * SS)          // 8192
#define ELEMS (BB * SS * DD)    // 8,388,608
#define KDIM 1024

#define NSEG 16
#define SEGL (SS / NSEG)
#define NC (BB * DD)
#define GSLICE 32

// ---------------------------------------------------------------------------
// Scratch (allocation-free: __device__ globals)
// ---------------------------------------------------------------------------
__device__ float g_r[ELEMS];
__device__ float g_k[ELEMS];
__device__ float g_v[ELEMS];
__device__ float g_wkv[ELEMS];

// bf16 hi/lo split activations
__device__ __nv_bfloat16 g_xrh[ELEMS];
__device__ __nv_bfloat16 g_xrl[ELEMS];
__device__ __nv_bfloat16 g_xkh[ELEMS];
__device__ __nv_bfloat16 g_xkl[ELEMS];
__device__ __nv_bfloat16 g_xvh[ELEMS];
__device__ __nv_bfloat16 g_xvl[ELEMS];

// bf16 hi/lo split weights
__device__ __nv_bfloat16 g_Wrh[DD * DD];
__device__ __nv_bfloat16 g_Wrl[DD * DD];
__device__ __nv_bfloat16 g_Wkh[DD * DD];
__device__ __nv_bfloat16 g_Wkl[DD * DD];
__device__ __nv_bfloat16 g_Wvh[DD * DD];
__device__ __nv_bfloat16 g_Wvl[DD * DD];
__device__ __nv_bfloat16 g_Woh[DD * DD];
__device__ __nv_bfloat16 g_Wol[DD * DD];

// WKV scan scratch
__device__ float g_bs[NSEG * NC];
__device__ float g_bin[NSEG * NC];
__device__ float g_Cc[NSEG * NC];
__device__ float g_lP[NSEG * NC];
__device__ float g_ain[NSEG * NC];

// GroupNorm scratch
__device__ float g_psum[BB * HH * GSLICE];
__device__ float g_psq[BB * HH * GSLICE];
__device__ float g_mean[BB * HH];
__device__ float g_rstd[BB * HH];

// ---------------------------------------------------------------------------
// helpers
// ---------------------------------------------------------------------------
__device__ __forceinline__ uint32_t smem_u32(const void* p) {
    uint32_t a;
    asm("{ .reg .u64 t; cvta.to.shared.u64 t, %1; cvt.u32.u64 %0, t; }"
        : "=r"(a) : "l"(p));
    return a;
}

__device__ __forceinline__ void cpa16(uint32_t s, const void* g) {
    asm volatile("cp.async.cg.shared.global [%0], [%1], 16;\n" :: "r"(s), "l"(g));
}
__device__ __forceinline__ void cpa_commit() {
    asm volatile("cp.async.commit_group;\n" ::: "memory");
}
template <int N>
__device__ __forceinline__ void cpa_wait() {
    asm volatile("cp.async.wait_group %0;\n" :: "n"(N) : "memory");
}

__device__ __forceinline__ void ldsm4(uint32_t* r, uint32_t addr) {
    asm volatile(
        "ldmatrix.sync.aligned.m8n8.x4.shared.b16 {%0,%1,%2,%3}, [%4];"
        : "=r"(r[0]), "=r"(r[1]), "=r"(r[2]), "=r"(r[3]) : "r"(addr));
}

__device__ __forceinline__ void mma_bf16(float* c, const uint32_t* a,
                                         uint32_t b0, uint32_t b1) {
    asm volatile(
        "mma.sync.aligned.m16n8k16.row.col.f32.bf16.bf16.f32 "
        "{%0,%1,%2,%3}, {%4,%5,%6,%7}, {%8,%9}, {%0,%1,%2,%3};\n"
        : "+f"(c[0]), "+f"(c[1]), "+f"(c[2]), "+f"(c[3])
        : "r"(a[0]), "r"(a[1]), "r"(a[2]), "r"(a[3]), "r"(b0), "r"(b1));
}

// split helper: hi = bf16_rn(x), lo = bf16_rn(x - hi)
__device__ __forceinline__ void split2(float a, float b, uint32_t& hi, uint32_t& lo) {
    __nv_bfloat16 ha = __float2bfloat16(a);
    __nv_bfloat16 hb = __float2bfloat16(b);
    __nv_bfloat16 la = __float2bfloat16(a - __bfloat162float(ha));
    __nv_bfloat16 lb = __float2bfloat16(b - __bfloat162float(hb));
    __nv_bfloat162 h = __nv_bfloat162(ha, hb);
    __nv_bfloat162 l = __nv_bfloat162(la, lb);
    hi = *(uint32_t*)&h;
    lo = *(uint32_t*)&l;
}

// ---------------------------------------------------------------------------
// Kernel: split all 4 weight matrices into bf16 hi/lo (single launch)
// ---------------------------------------------------------------------------
__global__ void split_w4(const float* __restrict__ W0, const float* __restrict__ W1,
                         const float* __restrict__ W2, const float* __restrict__ W3,
                         __nv_bfloat16* __restrict__ H0, __nv_bfloat16* __restrict__ L0,
                         __nv_bfloat16* __restrict__ H1, __nv_bfloat16* __restrict__ L1,
                         __nv_bfloat16* __restrict__ H2, __nv_bfloat16* __restrict__ L2,
                         __nv_bfloat16* __restrict__ H3, __nv_bfloat16* __restrict__ L3) {
    const int N4 = DD * DD / 4;
    int idx = blockIdx.x * blockDim.x + threadIdx.x;
    if (idx >= 4 * N4) return;
    int m = idx / N4;
    int i = idx - m * N4;
    const float* W = (m == 0) ? W0 : (m == 1) ? W1 : (m == 2) ? W2 : W3;
    __nv_bfloat16* H = (m == 0) ? H0 : (m == 1) ? H1 : (m == 2) ? H2 : H3;
    __nv_bfloat16* L = (m == 0) ? L0 : (m == 1) ? L1 : (m == 2) ? L2 : L3;
    float4 a = ((const float4*)W)[i];
    uint2 h, l;
    split2(a.x, a.y, h.x, l.x);
    split2(a.z, a.w, h.y, l.y);
    ((uint2*)H)[i] = h;
    ((uint2*)L)[i] = l;
}

// ---------------------------------------------------------------------------
// Kernel: token shift + mixing -> bf16 hi/lo of xr, xk, xv
// ---------------------------------------------------------------------------
__global__ void mix_kernel(const float* __restrict__ x,
                           const float* __restrict__ tmr,
                           const float* __restrict__ tmk,
                           const float* __restrict__ tmv) {
    int idx = blockIdx.x * blockDim.x + threadIdx.x;
    const int TOT4 = ELEMS / 4;
    if (idx >= TOT4) return;
    const int D4 = DD / 4;
    int d4 = idx % D4;
    int bs = idx / D4;
    int s = bs % SS;

    const float4* x4 = (const float4*)x;
    float4 xv_ = x4[idx];
    float4 sh = (s > 0) ? x4[idx - D4] : make_float4(0.f, 0.f, 0.f, 0.f);
    float4 mr = ((const float4*)tmr)[d4];
    float4 mk = ((const float4*)tmk)[d4];
    float4 mv = ((const float4*)tmv)[d4];

    float4 orr, okk, ovv;
    orr.x = xv_.x * mr.x + sh.x * (1.f - mr.x);
    orr.y = xv_.y * mr.y + sh.y * (1.f - mr.y);
    orr.z = xv_.z * mr.z + sh.z * (1.f - mr.z);
    orr.w = xv_.w * mr.w + sh.w * (1.f - mr.w);
    okk.x = xv_.x * mk.x + sh.x * (1.f - mk.x);
    okk.y = xv_.y * mk.y + sh.y * (1.f - mk.y);
    okk.z = xv_.z * mk.z + sh.z * (1.f - mk.z);
    okk.w = xv_.w * mk.w + sh.w * (1.f - mk.w);
    ovv.x = xv_.x * mv.x + sh.x * (1.f - mv.x);
    ovv.y = xv_.y * mv.y + sh.y * (1.f - mv.y);
    ovv.z = xv_.z * mv.z + sh.z * (1.f - mv.z);
    ovv.w = xv_.w * mv.w + sh.w * (1.f - mv.w);

    uint2 h, l;
    split2(orr.x, orr.y, h.x, l.x); split2(orr.z, orr.w, h.y, l.y);
    ((uint2*)g_xrh)[idx] = h; ((uint2*)g_xrl)[idx] = l;
    split2(okk.x, okk.y, h.x, l.x); split2(okk.z, okk.w, h.y, l.y);
    ((uint2*)g_xkh)[idx] = h; ((uint2*)g_xkl)[idx] = l;
    split2(ovv.x, ovv.y, h.x, l.x); split2(ovv.z, ovv.w, h.y, l.y);
    ((uint2*)g_xvh)[idx] = h; ((uint2*)g_xvl)[idx] = l;
}

// ---------------------------------------------------------------------------
// bf16-split tensor-core GEMM (ldmatrix feed):
//   C[8192,1024] = (Ah+Al)*(Bh+Bl)^T, fp32 out, 3 products ahbh+ahbl+albh.
// 128x128 CTA tile, 8 warps (2x4), warp tile 64x32, k-chunk 32,
// cp.async double buffer. blockIdx.z selects one of up to 3 operand sets.
// ---------------------------------------------------------------------------
#define WR 20                       // 32-bit words per smem row (16 data + 4 pad)
#define PART_WORDS (128 * WR)       // 2560 words per tile part
#define BUF_WORDS (4 * PART_WORDS)  // Ahi, Alo, Bhi, Blo
#define GSM_BYTES (2 * BUF_WORDS * 4)  // 81920

__global__ __launch_bounds__(256, 2)
void gemm3(const __nv_bfloat16* __restrict__ Ah0, const __nv_bfloat16* __restrict__ Al0,
           const __nv_bfloat16* __restrict__ Bh0, const __nv_bfloat16* __restrict__ Bl0,
           float* __restrict__ C0,
           const __nv_bfloat16* __restrict__ Ah1, const __nv_bfloat16* __restrict__ Al1,
           const __nv_bfloat16* __restrict__ Bh1, const __nv_bfloat16* __restrict__ Bl1,
           float* __restrict__ C1,
           const __nv_bfloat16* __restrict__ Ah2, const __nv_bfloat16* __restrict__ Al2,
           const __nv_bfloat16* __restrict__ Bh2, const __nv_bfloat16* __restrict__ Bl2,
           float* __restrict__ C2) {
    extern __shared__ uint32_t sm[];
    const uint32_t smb = smem_u32(sm);
    const int z = blockIdx.z;
    const __nv_bfloat16* Ah = (z == 0) ? Ah0 : (z == 1) ? Ah1 : Ah2;
    const __nv_bfloat16* Al = (z == 0) ? Al0 : (z == 1) ? Al1 : Al2;
    const __nv_bfloat16* Bh = (z == 0) ? Bh0 : (z == 1) ? Bh1 : Bh2;
    const __nv_bfloat16* Bl = (z == 0) ? Bl0 : (z == 1) ? Bl1 : Bl2;
    float* C = (z == 0) ? C0 : (z == 1) ? C1 : C2;

    const int tid = threadIdx.x;
    const int lane = tid & 31;
    const int wid = tid >> 5;
    const int wm = wid >> 2;       // 0..1
    const int wn = wid & 3;        // 0..3
    const int bm = blockIdx.y * 128;
    const int bn = blockIdx.x * 128;

    const __nv_bfloat16* src[4] = {
        Ah + (size_t)bm * KDIM, Al + (size_t)bm * KDIM,
        Bh + (size_t)bn * KDIM, Bl + (size_t)bn * KDIM};

    float c[4][4][4];
#pragma unroll
    for (int i = 0; i < 4; i++)
#pragma unroll
        for (int j = 0; j < 4; j++)
#pragma unroll
            for (int q = 0; q < 4; q++) c[i][j][q] = 0.f;

    auto load_stage = [&](int buf, int k0) {
#pragma unroll
        for (int i = 0; i < 8; i++) {
            int id = tid + i * 256;
            int part = id >> 9;
            int pid = id & 511;
            int row = pid >> 2;
            int wc = pid & 3;
            uint32_t saddr =
                smb + (uint32_t)(buf * BUF_WORDS + part * PART_WORDS +
                                 row * WR + wc * 4) * 4u;
            cpa16(saddr, src[part] + (size_t)row * KDIM + k0 + wc * 8);
        }
    };

    // ldmatrix lane addressing (row = +lane&15, word = +(lane>>4)*4)
    const uint32_t lrow = (uint32_t)(lane & 15);
    const uint32_t lwoff = (uint32_t)((lane >> 4) << 2);

    load_stage(0, 0);
    cpa_commit();

#pragma unroll 1
    for (int it = 0; it < 32; ++it) {
        if (it + 1 < 32) {
            load_stage((it + 1) & 1, (it + 1) * 32);
            cpa_commit();
            cpa_wait<1>();
        } else {
            cpa_wait<0>();
        }
        __syncthreads();

        const uint32_t base = smb + (uint32_t)((it & 1) * BUF_WORDS) * 4u;
        const uint32_t baseAh = base;
        const uint32_t baseAl = base + PART_WORDS * 4u;
        const uint32_t baseBh = base + 2u * PART_WORDS * 4u;
        const uint32_t baseBl = base + 3u * PART_WORDS * 4u;

#pragma unroll
        for (int ks = 0; ks < 2; ks++) {
            const uint32_t woff = (uint32_t)(ks * 8) + lwoff;
            // B fragments: 2 n-pairs x (hi,lo), each ldmatrix.x4 covers 16 n-rows
            uint32_t bh[2][4], bl[2][4];
#pragma unroll
            for (int np = 0; np < 2; np++) {
                uint32_t row = (uint32_t)(wn * 32 + np * 16) + lrow;
                ldsm4(bh[np], baseBh + (row * WR + woff) * 4u);
                ldsm4(bl[np], baseBl + (row * WR + woff) * 4u);
            }
#pragma unroll
            for (int mi = 0; mi < 4; mi++) {
                uint32_t arow = (uint32_t)(wm * 64 + mi * 16) + lrow;
                uint32_t ah[4], al[4];
                ldsm4(ah, baseAh + (arow * WR + woff) * 4u);
                ldsm4(al, baseAl + (arow * WR + woff) * 4u);
#pragma unroll
                for (int ni = 0; ni < 4; ni++) {
                    int np = ni >> 1, sel = ni & 1;
                    uint32_t b0h = bh[np][sel], b1h = bh[np][sel + 2];
                    uint32_t b0l = bl[np][sel], b1l = bl[np][sel + 2];
                    mma_bf16(c[mi][ni], ah, b0h, b1h);
                    mma_bf16(c[mi][ni], ah, b0l, b1l);
                    mma_bf16(c[mi][ni], al, b0h, b1h);
                }
            }
        }
        __syncthreads();
    }

    // writeback
#pragma unroll
    for (int mi = 0; mi < 4; mi++) {
        int r0 = bm + wm * 64 + mi * 16 + (lane >> 2);
#pragma unroll
        for (int ni = 0; ni < 4; ni++) {
            int col = bn + wn * 32 + ni * 8 + 2 * (lane & 3);
            float2 v01 = make_float2(c[mi][ni][0], c[mi][ni][1]);
            float2 v23 = make_float2(c[mi][ni][2], c[mi][ni][3]);
            *(float2*)(C + (size_t)r0 * DD + col) = v01;
            *(float2*)(C + (size_t)(r0 + 8) * DD + col) = v23;
        }
    }
}

// ---------------------------------------------------------------------------
// WKV segmented scan (validated)
// ---------------------------------------------------------------------------
__global__ void wkv_p1(const float* __restrict__ td) {
    int gid = blockIdx.x * blockDim.x + threadIdx.x;
    if (gid >= NSEG * NC) return;
    int c = gid % DD;
    int r = gid / DD;
    int b = r % BB;
    int seg = r / BB;
    float w = -__expf(td[c]);
    const float* kp = g_k + ((size_t)b * SS + (size_t)seg * SEGL) * DD + c;
    float bb = -1e38f;
#pragma unroll 4
    for (int t = 0; t < SEGL; t++) {
        float kt = kp[(size_t)t * DD];
        float ww = bb + w;
        float p2 = fmaxf(ww, kt);
        float e1 = __expf(ww - p2);
        float e2 = __expf(kt - p2);
        bb = p2 + __logf(e1 + e2 + 1e-8f);
    }
    g_bs[seg * NC + b * DD + c] = bb;
}

__global__ void wkv_p2(const float* __restrict__ td) {
    int ch = blockIdx.x * blockDim.x + threadIdx.x;
    if (ch >= NC) return;
    int c = ch % DD;
    float w = -__expf(td[c]);
    float Lw = (float)SEGL * w;
    float bin = -1e38f;
#pragma unroll
    for (int s = 0; s < NSEG; s++) {
        g_bin[s * NC + ch] = bin;
        float x = bin + Lw;
        float y = g_bs[s * NC + ch];
        float p = fmaxf(x, y);
        bin = p + __logf(__expf(x - p) + __expf(y - p));
    }
}

__global__ void wkv_p3(const float* __restrict__ td) {
    int gid = blockIdx.x * blockDim.x + threadIdx.x;
    if (gid >= NSEG * NC) return;
    int c = gid % DD;
    int r = gid / DD;
    int b = r % BB;
    int seg = r / BB;
    float w = -__expf(td[c]);
    const float* kp = g_k + ((size_t)b * SS + (size_t)seg * SEGL) * DD + c;
    const float* vp = g_v + ((size_t)b * SS + (size_t)seg * SEGL) * DD + c;
    int sidx = seg * NC + b * DD + c;
    float bb = g_bin[sidx];
    float aa = 0.f, lP = 0.f;
#pragma unroll 4
    for (int t = 0; t < SEGL; t++) {
        float kt = kp[(size_t)t * DD];
        float vt = vp[(size_t)t * DD];
        float ww = bb + w;
        float p2 = fmaxf(ww, kt);
        lP += ww - p2;
        float e1b = __expf(ww - p2);
        float e2b = __expf(kt - p2);
        aa = e1b * aa + e2b * vt;
        bb = p2 + __logf(e1b + e2b + 1e-8f);
    }
    g_Cc[sidx] = aa;
    g_lP[sidx] = lP;
}

__global__ void wkv_p4() {
    int ch = blockIdx.x * blockDim.x + threadIdx.x;
    if (ch >= NC) return;
    float ain = 0.f;
#pragma unroll
    for (int s = 0; s < NSEG; s++) {
        g_ain[s * NC + ch] = ain;
        ain = __expf(g_lP[s * NC + ch]) * ain + g_Cc[s * NC + ch];
    }
}

__global__ void wkv_p5(const float* __restrict__ td, const float* __restrict__ tf) {
    int gid = blockIdx.x * blockDim.x + threadIdx.x;
    if (gid >= NSEG * NC) return;
    int c = gid % DD;
    int r = gid / DD;
    int b = r % BB;
    int seg = r / BB;
    float w = -__expf(td[c]);
    float u = tf[c];
    size_t off0 = ((size_t)b * SS + (size_t)seg * SEGL) * DD + c;
    const float* kp = g_k + off0;
    const float* vp = g_v + off0;
    float* op = g_wkv + off0;
    int sidx = seg * NC + b * DD + c;
    float aa = g_ain[sidx];
    float bb = g_bin[sidx];
#pragma unroll 2
    for (int t = 0; t < SEGL; t++) {
        float kt = kp[(size_t)t * DD];
        float vt = vp[(size_t)t * DD];
        float wk = kt + u;
        float p = fmaxf(bb, wk);
        float e1 = __expf(bb - p);
        float e2 = __expf(wk - p);
        op[(size_t)t * DD] = (e1 * aa + e2 * vt) / (e1 + e2 + 1e-8f);
        float ww = bb + w;
        float p2 = fmaxf(ww, kt);
        float e1b = __expf(ww - p2);
        float e2b = __expf(kt - p2);
        aa = e1b * aa + e2b * vt;
        bb = p2 + __logf(e1b + e2b + 1e-8f);
    }
}

// ---------------------------------------------------------------------------
// GroupNorm (3 phases); normed output -> bf16 hi/lo (g_xrh/g_xrl reuse)
// ---------------------------------------------------------------------------
__global__ __launch_bounds__(256)
void gn_sum() {
    const int grp = blockIdx.y;
    const int slice = blockIdx.x;
    const int b = grp / HH;
    const int h = grp % HH;
    const size_t base = (size_t)b * SS * DD + (size_t)h * HD;
    const int tid = threadIdx.x;
    const int SROWS = SS / GSLICE;

    float sum = 0.f, sq = 0.f;
    for (int j = tid; j < SROWS * HD; j += 256) {
        int s = slice * SROWS + (j >> 6);
        int i = j & 63;
        size_t off = base + (size_t)s * DD + i;
        float y = g_wkv[off] / (1.f + __expf(-g_r[off]));
        g_wkv[off] = y;
        sum += y;
        sq += y * y;
    }

    __shared__ float r1[256], r2[256];
    r1[tid] = sum; r2[tid] = sq;
    __syncthreads();
#pragma unroll
    for (int o = 128; o > 0; o >>= 1) {
        if (tid < o) { r1[tid] += r1[tid + o]; r2[tid] += r2[tid + o]; }
        __syncthreads();
    }
    if (tid == 0) {
        g_psum[grp * GSLICE + slice] = r1[0];
        g_psq[grp * GSLICE + slice] = r2[0];
    }
}

__global__ void gn_mid() {
    int g = threadIdx.x;
    if (g >= BB * HH) return;
    float s = 0.f, q = 0.f;
#pragma unroll
    for (int i = 0; i < GSLICE; i++) {
        s += g_psum[g * GSLICE + i];
        q += g_psq[g * GSLICE + i];
    }
    const float inv = 1.f / (float)(SS * HD);
    float mean = s * inv;
    float var = q * inv - mean * mean;
    g_mean[g] = mean;
    g_rstd[g] = rsqrtf(var + 1e-5f);
}

__global__ void gn_norm(const float* __restrict__ gamma,
                        const float* __restrict__ beta) {
    int idx = blockIdx.x * blockDim.x + threadIdx.x;
    const int TOT4 = ELEMS / 4;
    if (idx >= TOT4) return;
    const int D4 = DD / 4;
    int d4 = idx % D4;
    int bs = idx / D4;
    int b = bs / SS;
    int c0 = d4 * 4;
    int h = c0 / HD;
    int grp = b * HH + h;
    float mean = g_mean[grp];
    float rstd = g_rstd[grp];
    float4 y = ((const float4*)g_wkv)[idx];
    float4 ga = ((const float4*)gamma)[d4];
    float4 be = ((const float4*)beta)[d4];
    float4 o;
    o.x = (y.x - mean) * rstd * ga.x + be.x;
    o.y = (y.y - mean) * rstd * ga.y + be.y;
    o.z = (y.z - mean) * rstd * ga.z + be.z;
    o.w = (y.w - mean) * rstd * ga.w + be.w;
    uint2 hh, ll;
    split2(o.x, o.y, hh.x, ll.x);
    split2(o.z, o.w, hh.y, ll.y);
    ((uint2*)g_xrh)[idx] = hh;
    ((uint2*)g_xrl)[idx] = ll;
}

// ---------------------------------------------------------------------------
// Launch
// ---------------------------------------------------------------------------
extern "C" void kernel_launch(void* const* d_in, const int* in_sizes, int n_in,
                              void* d_out, int out_size) {
    const float* x     = (const float*)d_in[0];
    const float* tmr   = (const float*)d_in[1];
    const float* tmk   = (const float*)d_in[2];
    const float* tmv   = (const float*)d_in[3];
    const float* Wr    = (const float*)d_in[4];
    const float* Wk    = (const float*)d_in[5];
    const float* Wv    = (const float*)d_in[6];
    const float* Wo    = (const float*)d_in[7];
    const float* td    = (const float*)d_in[8];
    const float* tf    = (const float*)d_in[9];
    const float* gamma = (const float*)d_in[10];
    const float* beta  = (const float*)d_in[11];
    float* out = (float*)d_out;

    float *r, *k, *v;
    __nv_bfloat16 *xrh, *xrl, *xkh, *xkl, *xvh, *xvl;
    __nv_bfloat16 *wrh, *wrl, *wkh, *wkl, *wvh, *wvl, *woh, *wol;
    cudaGetSymbolAddress((void**)&r, g_r);
    cudaGetSymbolAddress((void**)&k, g_k);
    cudaGetSymbolAddress((void**)&v, g_v);
    cudaGetSymbolAddress((void**)&xrh, g_xrh);
    cudaGetSymbolAddress((void**)&xrl, g_xrl);
    cudaGetSymbolAddress((void**)&xkh, g_xkh);
    cudaGetSymbolAddress((void**)&xkl, g_xkl);
    cudaGetSymbolAddress((void**)&xvh, g_xvh);
    cudaGetSymbolAddress((void**)&xvl, g_xvl);
    cudaGetSymbolAddress((void**)&wrh, g_Wrh);
    cudaGetSymbolAddress((void**)&wrl, g_Wrl);
    cudaGetSymbolAddress((void**)&wkh, g_Wkh);
    cudaGetSymbolAddress((void**)&wkl, g_Wkl);
    cudaGetSymbolAddress((void**)&wvh, g_Wvh);
    cudaGetSymbolAddress((void**)&wvl, g_Wvl);
    cudaGetSymbolAddress((void**)&woh, g_Woh);
    cudaGetSymbolAddress((void**)&wol, g_Wol);

    cudaFuncSetAttribute(gemm3,
                         cudaFuncAttributeMaxDynamicSharedMemorySize, GSM_BYTES);

    // 1. split weights (one launch) + token-shift mixing
    const int WB4 = (4 * DD * DD / 4 + 255) / 256;
    split_w4<<<WB4, 256>>>(Wr, Wk, Wv, Wo, wrh, wrl, wkh, wkl, wvh, wvl, woh, wol);
    mix_kernel<<<(ELEMS / 4 + 255) / 256, 256>>>(x, tmr, tmk, tmv);

    // 2. r/k/v projections: one batched launch, z selects operand set
    dim3 gg3(DD / 128, MTOT / 128, 3);
    gemm3<<<gg3, 256, GSM_BYTES>>>(xrh, xrl, wrh, wrl, r,
                                   xkh, xkl, wkh, wkl, k,
                                   xvh, xvl, wvh, wvl, v);

    // 3. segmented WKV scan
    wkv_p1<<<(NSEG * NC + 255) / 256, 256>>>(td);
    wkv_p2<<<(NC + 255) / 256, 256>>>(td);
    wkv_p3<<<(NSEG * NC + 255) / 256, 256>>>(td);
    wkv_p4<<<(NC + 255) / 256, 256>>>();
    wkv_p5<<<(NSEG * NC + 255) / 256, 256>>>(td, tf);

    // 4. sigmoid gate + group norm (split output into g_xrh/g_xrl)
    dim3 gns(GSLICE, BB * HH);
    gn_sum<<<gns, 256>>>();
    gn_mid<<<1, 64>>>();
    gn_norm<<<(ELEMS / 4 + 255) / 256, 256>>>(gamma, beta);

    // 5. output projection (z=1)
    dim3 gg1(DD / 128, MTOT / 128, 1);
    gemm3<<<gg1, 256, GSM_BYTES>>>(xrh, xrl, woh, wol, out,
                                   xrh, xrl, woh, wol, out,
                                   xrh, xrl, woh, wol, out);
}

// round 6
// speedup vs baseline: 7.4962x; 2.0685x over previous
#include <cuda_runtime.h>
#include <cuda_fp16.h>
#include <math.h>
#include <cstdint>

// Problem constants
#define BB 4
#define SS 2048
#define DD 1024
#define HH 16
#define HD 64
#define MTOT (BB * SS)          // 8192
#define ELEMS (BB * SS * DD)    // 8,388,608
#define KDIM 1024

#define NSEG 32
#define SEGL (SS / NSEG)        // 64
#define NC (BB * DD)            // 4096
#define GSLICE 32

// ---------------------------------------------------------------------------
// Scratch (allocation-free: __device__ globals)
// ---------------------------------------------------------------------------
__device__ float g_r[ELEMS];
__device__ float g_k[ELEMS];
__device__ float g_v[ELEMS];
__device__ float g_wkv[ELEMS];

// fp16 activations
__device__ __half g_hxr[ELEMS];
__device__ __half g_hxk[ELEMS];
__device__ __half g_hxv[ELEMS];

// fp16 weights
__device__ __half g_hWr[DD * DD];
__device__ __half g_hWk[DD * DD];
__device__ __half g_hWv[DD * DD];
__device__ __half g_hWo[DD * DD];

// WKV scan scratch
__device__ float g_bs[NSEG * NC];
__device__ float g_bin[NSEG * NC];
__device__ float g_Cc[NSEG * NC];
__device__ float g_lP[NSEG * NC];
__device__ float g_ain[NSEG * NC];

// GroupNorm scratch
__device__ float g_psum[BB * HH * GSLICE];
__device__ float g_psq[BB * HH * GSLICE];
__device__ float g_mean[BB * HH];
__device__ float g_rstd[BB * HH];

// ---------------------------------------------------------------------------
// helpers
// ---------------------------------------------------------------------------
__device__ __forceinline__ uint32_t smem_u32(const void* p) {
    uint32_t a;
    asm("{ .reg .u64 t; cvta.to.shared.u64 t, %1; cvt.u32.u64 %0, t; }"
        : "=r"(a) : "l"(p));
    return a;
}

__device__ __forceinline__ void cpa16(uint32_t s, const void* g) {
    asm volatile("cp.async.cg.shared.global [%0], [%1], 16;\n" :: "r"(s), "l"(g));
}
__device__ __forceinline__ void cpa_commit() {
    asm volatile("cp.async.commit_group;\n" ::: "memory");
}
template <int N>
__device__ __forceinline__ void cpa_wait() {
    asm volatile("cp.async.wait_group %0;\n" :: "n"(N) : "memory");
}

__device__ __forceinline__ void ldsm4(uint32_t* r, uint32_t addr) {
    asm volatile(
        "ldmatrix.sync.aligned.m8n8.x4.shared.b16 {%0,%1,%2,%3}, [%4];"
        : "=r"(r[0]), "=r"(r[1]), "=r"(r[2]), "=r"(r[3]) : "r"(addr));
}

__device__ __forceinline__ void mma_f16(float* c, const uint32_t* a,
                                        uint32_t b0, uint32_t b1) {
    asm volatile(
        "mma.sync.aligned.m16n8k16.row.col.f32.f16.f16.f32 "
        "{%0,%1,%2,%3}, {%4,%5,%6,%7}, {%8,%9}, {%0,%1,%2,%3};\n"
        : "+f"(c[0]), "+f"(c[1]), "+f"(c[2]), "+f"(c[3])
        : "r"(a[0]), "r"(a[1]), "r"(a[2]), "r"(a[3]), "r"(b0), "r"(b1));
}

__device__ __forceinline__ uint32_t pack_h2(float a, float b) {
    __half2 h = __float22half2_rn(make_float2(a, b));
    return *(uint32_t*)&h;
}

// ---------------------------------------------------------------------------
// Kernel: convert 4 weight matrices fp32 -> fp16 (single launch)
// ---------------------------------------------------------------------------
__global__ void prep_w4(const float* __restrict__ W0, const float* __restrict__ W1,
                        const float* __restrict__ W2, const float* __restrict__ W3,
                        __half* __restrict__ H0, __half* __restrict__ H1,
                        __half* __restrict__ H2, __half* __restrict__ H3) {
    const int N4 = DD * DD / 4;
    int idx = blockIdx.x * blockDim.x + threadIdx.x;
    if (idx >= 4 * N4) return;
    int m = idx / N4;
    int i = idx - m * N4;
    const float* W = (m == 0) ? W0 : (m == 1) ? W1 : (m == 2) ? W2 : W3;
    __half* H = (m == 0) ? H0 : (m == 1) ? H1 : (m == 2) ? H2 : H3;
    float4 a = ((const float4*)W)[i];
    uint2 h;
    h.x = pack_h2(a.x, a.y);
    h.y = pack_h2(a.z, a.w);
    ((uint2*)H)[i] = h;
}

// ---------------------------------------------------------------------------
// Kernel: token shift + mixing -> fp16 xr, xk, xv
// ---------------------------------------------------------------------------
__global__ void mix_kernel(const float* __restrict__ x,
                           const float* __restrict__ tmr,
                           const float* __restrict__ tmk,
                           const float* __restrict__ tmv) {
    int idx = blockIdx.x * blockDim.x + threadIdx.x;
    const int TOT4 = ELEMS / 4;
    if (idx >= TOT4) return;
    const int D4 = DD / 4;
    int d4 = idx % D4;
    int bs = idx / D4;
    int s = bs % SS;

    const float4* x4 = (const float4*)x;
    float4 xv_ = x4[idx];
    float4 sh = (s > 0) ? x4[idx - D4] : make_float4(0.f, 0.f, 0.f, 0.f);
    float4 mr = ((const float4*)tmr)[d4];
    float4 mk = ((const float4*)tmk)[d4];
    float4 mv = ((const float4*)tmv)[d4];

    uint2 h;
    h.x = pack_h2(xv_.x * mr.x + sh.x * (1.f - mr.x),
                  xv_.y * mr.y + sh.y * (1.f - mr.y));
    h.y = pack_h2(xv_.z * mr.z + sh.z * (1.f - mr.z),
                  xv_.w * mr.w + sh.w * (1.f - mr.w));
    ((uint2*)g_hxr)[idx] = h;
    h.x = pack_h2(xv_.x * mk.x + sh.x * (1.f - mk.x),
                  xv_.y * mk.y + sh.y * (1.f - mk.y));
    h.y = pack_h2(xv_.z * mk.z + sh.z * (1.f - mk.z),
                  xv_.w * mk.w + sh.w * (1.f - mk.w));
    ((uint2*)g_hxk)[idx] = h;
    h.x = pack_h2(xv_.x * mv.x + sh.x * (1.f - mv.x),
                  xv_.y * mv.y + sh.y * (1.f - mv.y));
    h.y = pack_h2(xv_.z * mv.z + sh.z * (1.f - mv.z),
                  xv_.w * mv.w + sh.w * (1.f - mv.w));
    ((uint2*)g_hxv)[idx] = h;
}

// ---------------------------------------------------------------------------
// fp16 tensor-core GEMM: C[8192,1024] = A[8192,1024] * B[1024,1024]^T, fp32 out
// 128x128 CTA tile, 8 warps (2x4), warp tile 64x32, k-chunk 32,
// 3-stage cp.async pipeline, ldmatrix feed. blockIdx.z selects operand set.
// ---------------------------------------------------------------------------
#define WRB 80                     // bytes per smem row (64 data + 16 pad)
#define PART_B (128 * WRB)         // 10240 bytes (one 128x32 fp16 tile)
#define STAGE_B (2 * PART_B)       // 20480 (A + B)
#define GSM_BYTES (3 * STAGE_B)    // 61440

__global__ __launch_bounds__(256, 2)
void gemm_h(const __half* __restrict__ A0, const __half* __restrict__ B0,
            float* __restrict__ C0,
            const __half* __restrict__ A1, const __half* __restrict__ B1,
            float* __restrict__ C1,
            const __half* __restrict__ A2, const __half* __restrict__ B2,
            float* __restrict__ C2) {
    extern __shared__ char smc[];
    const uint32_t smb = smem_u32(smc);
    const int z = blockIdx.z;
    const __half* A = (z == 0) ? A0 : (z == 1) ? A1 : A2;
    const __half* Bm = (z == 0) ? B0 : (z == 1) ? B1 : B2;
    float* C = (z == 0) ? C0 : (z == 1) ? C1 : C2;

    const int tid = threadIdx.x;
    const int lane = tid & 31;
    const int wid = tid >> 5;
    const int wm = wid >> 2;       // 0..1
    const int wn = wid & 3;        // 0..3
    const int bm = blockIdx.y * 128;
    const int bn = blockIdx.x * 128;

    const __half* srcA = A + (size_t)bm * KDIM;
    const __half* srcB = Bm + (size_t)bn * KDIM;

    float c[4][4][4];
#pragma unroll
    for (int i = 0; i < 4; i++)
#pragma unroll
        for (int j = 0; j < 4; j++)
#pragma unroll
            for (int q = 0; q < 4; q++) c[i][j][q] = 0.f;

    auto load_stage = [&](int buf, int k0) {
#pragma unroll
        for (int i = 0; i < 4; i++) {
            int id = tid + i * 256;           // 0..1023
            int part = id >> 9;               // 0 = A, 1 = B
            int pid = id & 511;
            int row = pid >> 2;               // 0..127
            int cc = pid & 3;                 // 16B chunk within row
            uint32_t saddr = smb + (uint32_t)(buf * STAGE_B + part * PART_B +
                                              row * WRB + cc * 16);
            const __half* g = (part == 0 ? srcA : srcB) + (size_t)row * KDIM +
                              k0 + cc * 8;
            cpa16(saddr, g);
        }
    };

    const uint32_t lrow = (uint32_t)(lane & 15);
    const uint32_t lhalf = (uint32_t)((lane >> 4) << 4);  // 0 or 16 bytes

    load_stage(0, 0); cpa_commit();
    load_stage(1, 32); cpa_commit();

#pragma unroll 1
    for (int it = 0; it < 32; ++it) {
        if (it < 31) cpa_wait<1>(); else cpa_wait<0>();
        __syncthreads();
        if (it + 2 < 32) {
            load_stage((it + 2) % 3, (it + 2) * 32);
            cpa_commit();
        }

        const uint32_t baseA = smb + (uint32_t)((it % 3) * STAGE_B);
        const uint32_t baseB = baseA + PART_B;

#pragma unroll
        for (int ks = 0; ks < 2; ks++) {
            const uint32_t koff = (uint32_t)(ks * 32) + lhalf;
            uint32_t bf[2][4];
#pragma unroll
            for (int np = 0; np < 2; np++) {
                uint32_t row = (uint32_t)(wn * 32 + np * 16) + lrow;
                ldsm4(bf[np], baseB + row * WRB + koff);
            }
#pragma unroll
            for (int mi = 0; mi < 4; mi++) {
                uint32_t arow = (uint32_t)(wm * 64 + mi * 16) + lrow;
                uint32_t ah[4];
                ldsm4(ah, baseA + arow * WRB + koff);
#pragma unroll
                for (int ni = 0; ni < 4; ni++) {
                    int np = ni >> 1, sel = ni & 1;
                    mma_f16(c[mi][ni], ah, bf[np][sel], bf[np][sel + 2]);
                }
            }
        }
    }

    // writeback
#pragma unroll
    for (int mi = 0; mi < 4; mi++) {
        int r0 = bm + wm * 64 + mi * 16 + (lane >> 2);
#pragma unroll
        for (int ni = 0; ni < 4; ni++) {
            int col = bn + wn * 32 + ni * 8 + 2 * (lane & 3);
            float2 v01 = make_float2(c[mi][ni][0], c[mi][ni][1]);
            float2 v23 = make_float2(c[mi][ni][2], c[mi][ni][3]);
            *(float2*)(C + (size_t)r0 * DD + col) = v01;
            *(float2*)(C + (size_t)(r0 + 8) * DD + col) = v23;
        }
    }
}

// ---------------------------------------------------------------------------
// WKV segmented scan
// ---------------------------------------------------------------------------
__global__ void wkv_p1(const float* __restrict__ td) {
    int gid = blockIdx.x * blockDim.x + threadIdx.x;
    if (gid >= NSEG * NC) return;
    int c = gid % DD;
    int r = gid / DD;
    int b = r % BB;
    int seg = r / BB;
    float w = -__expf(td[c]);
    const float* kp = g_k + ((size_t)b * SS + (size_t)seg * SEGL) * DD + c;
    float bb = -1e38f;
#pragma unroll 4
    for (int t = 0; t < SEGL; t++) {
        float kt = kp[(size_t)t * DD];
        float ww = bb + w;
        float p2 = fmaxf(ww, kt);
        float e1 = __expf(ww - p2);
        float e2 = __expf(kt - p2);
        bb = p2 + __logf(e1 + e2 + 1e-8f);
    }
    g_bs[seg * NC + b * DD + c] = bb;
}

__global__ void wkv_p2(const float* __restrict__ td) {
    int ch = blockIdx.x * blockDim.x + threadIdx.x;
    if (ch >= NC) return;
    int c = ch % DD;
    float w = -__expf(td[c]);
    float Lw = (float)SEGL * w;
    float bin = -1e38f;
#pragma unroll
    for (int s = 0; s < NSEG; s++) {
        g_bin[s * NC + ch] = bin;
        float x = bin + Lw;
        float y = g_bs[s * NC + ch];
        float p = fmaxf(x, y);
        bin = p + __logf(__expf(x - p) + __expf(y - p));
    }
}

__global__ void wkv_p3(const float* __restrict__ td) {
    int gid = blockIdx.x * blockDim.x + threadIdx.x;
    if (gid >= NSEG * NC) return;
    int c = gid % DD;
    int r = gid / DD;
    int b = r % BB;
    int seg = r / BB;
    float w = -__expf(td[c]);
    const float* kp = g_k + ((size_t)b * SS + (size_t)seg * SEGL) * DD + c;
    const float* vp = g_v + ((size_t)b * SS + (size_t)seg * SEGL) * DD + c;
    int sidx = seg * NC + b * DD + c;
    float bb = g_bin[sidx];
    float aa = 0.f, lP = 0.f;
#pragma unroll 4
    for (int t = 0; t < SEGL; t++) {
        float kt = kp[(size_t)t * DD];
        float vt = vp[(size_t)t * DD];
        float ww = bb + w;
        float p2 = fmaxf(ww, kt);
        lP += ww - p2;
        float e1b = __expf(ww - p2);
        float e2b = __expf(kt - p2);
        aa = e1b * aa + e2b * vt;
        bb = p2 + __logf(e1b + e2b + 1e-8f);
    }
    g_Cc[sidx] = aa;
    g_lP[sidx] = lP;
}

__global__ void wkv_p4() {
    int ch = blockIdx.x * blockDim.x + threadIdx.x;
    if (ch >= NC) return;
    float ain = 0.f;
#pragma unroll
    for (int s = 0; s < NSEG; s++) {
        g_ain[s * NC + ch] = ain;
        ain = __expf(g_lP[s * NC + ch]) * ain + g_Cc[s * NC + ch];
    }
}

__global__ void wkv_p5(const float* __restrict__ td, const float* __restrict__ tf) {
    int gid = blockIdx.x * blockDim.x + threadIdx.x;
    if (gid >= NSEG * NC) return;
    int c = gid % DD;
    int r = gid / DD;
    int b = r % BB;
    int seg = r / BB;
    float w = -__expf(td[c]);
    float u = tf[c];
    size_t off0 = ((size_t)b * SS + (size_t)seg * SEGL) * DD + c;
    const float* kp = g_k + off0;
    const float* vp = g_v + off0;
    float* op = g_wkv + off0;
    int sidx = seg * NC + b * DD + c;
    float aa = g_ain[sidx];
    float bb = g_bin[sidx];
#pragma unroll 2
    for (int t = 0; t < SEGL; t++) {
        float kt = kp[(size_t)t * DD];
        float vt = vp[(size_t)t * DD];
        float wk = kt + u;
        float p = fmaxf(bb, wk);
        float e1 = __expf(bb - p);
        float e2 = __expf(wk - p);
        op[(size_t)t * DD] = (e1 * aa + e2 * vt) / (e1 + e2 + 1e-8f);
        float ww = bb + w;
        float p2 = fmaxf(ww, kt);
        float e1b = __expf(ww - p2);
        float e2b = __expf(kt - p2);
        aa = e1b * aa + e2b * vt;
        bb = p2 + __logf(e1b + e2b + 1e-8f);
    }
}

// ---------------------------------------------------------------------------
// GroupNorm (3 phases); normed output -> fp16 (g_hxr reuse)
// ---------------------------------------------------------------------------
__global__ __launch_bounds__(256)
void gn_sum() {
    const int grp = blockIdx.y;
    const int slice = blockIdx.x;
    const int b = grp / HH;
    const int h = grp % HH;
    const size_t base = (size_t)b * SS * DD + (size_t)h * HD;
    const int tid = threadIdx.x;
    const int SROWS = SS / GSLICE;

    float sum = 0.f, sq = 0.f;
    for (int j = tid; j < SROWS * HD; j += 256) {
        int s = slice * SROWS + (j >> 6);
        int i = j & 63;
        size_t off = base + (size_t)s * DD + i;
        float y = g_wkv[off] / (1.f + __expf(-g_r[off]));
        g_wkv[off] = y;
        sum += y;
        sq += y * y;
    }

    __shared__ float r1[256], r2[256];
    r1[tid] = sum; r2[tid] = sq;
    __syncthreads();
#pragma unroll
    for (int o = 128; o > 0; o >>= 1) {
        if (tid < o) { r1[tid] += r1[tid + o]; r2[tid] += r2[tid + o]; }
        __syncthreads();
    }
    if (tid == 0) {
        g_psum[grp * GSLICE + slice] = r1[0];
        g_psq[grp * GSLICE + slice] = r2[0];
    }
}

__global__ void gn_mid() {
    int g = threadIdx.x;
    if (g >= BB * HH) return;
    float s = 0.f, q = 0.f;
#pragma unroll
    for (int i = 0; i < GSLICE; i++) {
        s += g_psum[g * GSLICE + i];
        q += g_psq[g * GSLICE + i];
    }
    const float inv = 1.f / (float)(SS * HD);
    float mean = s * inv;
    float var = q * inv - mean * mean;
    g_mean[g] = mean;
    g_rstd[g] = rsqrtf(var + 1e-5f);
}

__global__ void gn_norm(const float* __restrict__ gamma,
                        const float* __restrict__ beta) {
    int idx = blockIdx.x * blockDim.x + threadIdx.x;
    const int TOT4 = ELEMS / 4;
    if (idx >= TOT4) return;
    const int D4 = DD / 4;
    int d4 = idx % D4;
    int bs = idx / D4;
    int b = bs / SS;
    int c0 = d4 * 4;
    int h = c0 / HD;
    int grp = b * HH + h;
    float mean = g_mean[grp];
    float rstd = g_rstd[grp];
    float4 y = ((const float4*)g_wkv)[idx];
    float4 ga = ((const float4*)gamma)[d4];
    float4 be = ((const float4*)beta)[d4];
    uint2 h2;
    h2.x = pack_h2((y.x - mean) * rstd * ga.x + be.x,
                   (y.y - mean) * rstd * ga.y + be.y);
    h2.y = pack_h2((y.z - mean) * rstd * ga.z + be.z,
                   (y.w - mean) * rstd * ga.w + be.w);
    ((uint2*)g_hxr)[idx] = h2;
}

// ---------------------------------------------------------------------------
// Launch
// ---------------------------------------------------------------------------
extern "C" void kernel_launch(void* const* d_in, const int* in_sizes, int n_in,
                              void* d_out, int out_size) {
    const float* x     = (const float*)d_in[0];
    const float* tmr   = (const float*)d_in[1];
    const float* tmk   = (const float*)d_in[2];
    const float* tmv   = (const float*)d_in[3];
    const float* Wr    = (const float*)d_in[4];
    const float* Wk    = (const float*)d_in[5];
    const float* Wv    = (const float*)d_in[6];
    const float* Wo    = (const float*)d_in[7];
    const float* td    = (const float*)d_in[8];
    const float* tf    = (const float*)d_in[9];
    const float* gamma = (const float*)d_in[10];
    const float* beta  = (const float*)d_in[11];
    float* out = (float*)d_out;

    float *r, *k, *v;
    __half *hxr, *hxk, *hxv, *hwr, *hwk, *hwv, *hwo;
    cudaGetSymbolAddress((void**)&r, g_r);
    cudaGetSymbolAddress((void**)&k, g_k);
    cudaGetSymbolAddress((void**)&v, g_v);
    cudaGetSymbolAddress((void**)&hxr, g_hxr);
    cudaGetSymbolAddress((void**)&hxk, g_hxk);
    cudaGetSymbolAddress((void**)&hxv, g_hxv);
    cudaGetSymbolAddress((void**)&hwr, g_hWr);
    cudaGetSymbolAddress((void**)&hwk, g_hWk);
    cudaGetSymbolAddress((void**)&hwv, g_hWv);
    cudaGetSymbolAddress((void**)&hwo, g_hWo);

    cudaFuncSetAttribute(gemm_h,
                         cudaFuncAttributeMaxDynamicSharedMemorySize, GSM_BYTES);

    // 1. weights -> fp16 (one launch) + token-shift mixing -> fp16
    const int WB4 = (DD * DD + 255) / 256;   // 4 * (DD*DD/4) elements of float4
    prep_w4<<<WB4, 256>>>(Wr, Wk, Wv, Wo, hwr, hwk, hwv, hwo);
    mix_kernel<<<(ELEMS / 4 + 255) / 256, 256>>>(x, tmr, tmk, tmv);

    // 2. r/k/v projections: one batched fp16 tensor-core launch
    dim3 gg3(DD / 128, MTOT / 128, 3);
    gemm_h<<<gg3, 256, GSM_BYTES>>>(hxr, hwr, r,
                                    hxk, hwk, k,
                                    hxv, hwv, v);

    // 3. segmented WKV scan
    wkv_p1<<<(NSEG * NC + 255) / 256, 256>>>(td);
    wkv_p2<<<(NC + 255) / 256, 256>>>(td);
    wkv_p3<<<(NSEG * NC + 255) / 256, 256>>>(td);
    wkv_p4<<<(NC + 255) / 256, 256>>>();
    wkv_p5<<<(NSEG * NC + 255) / 256, 256>>>(td, tf);

    // 4. sigmoid gate + group norm (fp16 output into g_hxr)
    dim3 gns(GSLICE, BB * HH);
    gn_sum<<<gns, 256>>>();
    gn_mid<<<1, 64>>>();
    gn_norm<<<(ELEMS / 4 + 255) / 256, 256>>>(gamma, beta);

    // 5. output projection
    dim3 gg1(DD / 128, MTOT / 128, 1);
    gemm_h<<<gg1, 256, GSM_BYTES>>>(hxr, hwo, out,
                                    hxr, hwo, out,
                                    hxr, hwo, out);
}